// round 7
// baseline (speedup 1.0000x reference)
#include <cuda_runtime.h>
#include <cuda_bf16.h>
#include <cstdint>

// Problem constants (shapes fixed by setup_inputs)
#define BSZ   4
#define LSZ   2048
#define KNB   30      // TOP_K
#define KPAD  32      // padded row stride for Fsm (128B, 16B-aligned float4 rows)
#define NRBF  16
#define NF    272     // 16 positional + 16 banks * 16 rbf
#define NOUT  128
#define MAXREL 32

// -------- device scratch (no cudaMalloc allowed) --------
__device__ float g_Cb  [BSZ*LSZ*3];
__device__ int   g_Eidx[BSZ*LSZ*KNB];
__device__ float g_Dsel[BSZ*LSZ*KNB];

// pair tables: dist(A_atom of residue i, B_atom of residue j)
// atom codes: 0=N (X[...,0]), 1=C (X[...,1]), 2=Ca (X[...,2]), 3=Cb (virtual)
__constant__ int c_PA[15] = {0,2,3,1,1,1,0,0,3,0,2,3,2,3,2};
__constant__ int c_PB[15] = {0,2,3,0,2,3,2,3,2,1,1,1,0,0,3};

// packed f32x2 FMA: d = a*b + d  (two independent IEEE fp32 FMAs, one instr)
__device__ __forceinline__ void ffma2(unsigned long long& d,
                                      unsigned long long a,
                                      unsigned long long b)
{
    asm("fma.rn.f32x2 %0, %1, %2, %0;" : "+l"(d) : "l"(a), "l"(b));
}

__device__ __forceinline__ unsigned long long pack_dup(float w)
{
    unsigned long long r;
    asm("mov.b64 %0, {%1, %1};" : "=l"(r) : "r"(__float_as_uint(w)));
    return r;
}

__device__ __forceinline__ void unpack2(unsigned long long v, float& lo, float& hi)
{
    asm("mov.b64 {%0, %1}, %2;" : "=f"(lo), "=f"(hi) : "l"(v));
}

// ============================================================
// Kernel 1: virtual C-beta per residue
// ============================================================
__global__ void cb_kernel(const float* __restrict__ X)
{
    int i = blockIdx.x * 256 + threadIdx.x;
    if (i >= BSZ*LSZ) return;
    const float* x = &X[i*12];
    float Nx=x[0],  Ny=x[1],  Nz=x[2];   // N  = X[:,:,0]
    float Cx=x[3],  Cy=x[4],  Cz=x[5];   // C  = X[:,:,1]
    float Ax=x[6],  Ay=x[7],  Az=x[8];   // Ca = X[:,:,2]
    float bx=Ax-Nx, by=Ay-Ny, bz=Az-Nz;          // b = Ca - N
    float cx=Cx-Ax, cy=Cy-Ay, cz=Cz-Az;          // c = C - Ca
    float ax = by*cz - bz*cy;                    // a = cross(b,c)
    float ay = bz*cx - bx*cz;
    float az = bx*cy - by*cx;
    g_Cb[i*3+0] = -0.58273431f*ax + 0.56802827f*bx - 0.54067466f*cx + Ax;
    g_Cb[i*3+1] = -0.58273431f*ay + 0.56802827f*by - 0.54067466f*cy + Ay;
    g_Cb[i*3+2] = -0.58273431f*az + 0.56802827f*bz - 0.54067466f*cz + Az;
}

// ============================================================
// Kernel 2: masked pairwise C-C distances + exact top-30
// Keys live in REGISTERS: key = (float_bits << 32) | j.
// min gives ascending distance; ties break to lower index,
// matching jax.lax.top_k stable order. Winner removal is by
// key equality (keys are unique thanks to the index bits).
// ============================================================
__global__ __launch_bounds__(256) void topk_kernel(
    const float* __restrict__ X, const float* __restrict__ mask,
    float* __restrict__ outIdxF)
{
    int row = blockIdx.x;           // b*L + i
    int b   = row / LSZ;
    int t   = threadIdx.x;
    int warp = t >> 5, lane = t & 31;

    __shared__ float wmax[8];
    __shared__ unsigned long long wmin[8];
    __shared__ float sDmax;
    __shared__ unsigned long long sBest;

    float cx = X[row*12+3], cy = X[row*12+4], cz = X[row*12+5];  // C atom
    float mi = mask[row];

    float dv[8], m2v[8];
    float lmax = 0.f;
    #pragma unroll
    for (int r = 0; r < 8; r++) {
        int j = t + r*256;
        const float* xj = &X[(b*LSZ + j)*12 + 3];
        float dx = cx-xj[0], dy = cy-xj[1], dz = cz-xj[2];
        float d  = sqrtf(dx*dx + dy*dy + dz*dz + 1e-6f);
        float m2 = mi * mask[b*LSZ + j];
        float md = m2 * d;
        dv[r]  = md;
        m2v[r] = m2;
        lmax = fmaxf(lmax, md);
    }
    #pragma unroll
    for (int o = 16; o > 0; o >>= 1) lmax = fmaxf(lmax, __shfl_xor_sync(0xffffffffu, lmax, o));
    if (lane == 0) wmax[warp] = lmax;
    __syncthreads();
    if (t == 0) {
        float m = wmax[0];
        for (int w = 1; w < 8; w++) m = fmaxf(m, wmax[w]);
        sDmax = m;
    }
    __syncthreads();
    float Dmax = sDmax;

    unsigned long long key[8];
    #pragma unroll
    for (int r = 0; r < 8; r++) {
        float adj = dv[r] + (1.0f - m2v[r]) * Dmax;      // D_adjust
        key[r] = ((unsigned long long)__float_as_uint(adj) << 32)
               | (unsigned)(t + r*256);
    }

    for (int it = 0; it < KNB; it++) {
        unsigned long long best = key[0];
        #pragma unroll
        for (int r = 1; r < 8; r++) if (key[r] < best) best = key[r];
        #pragma unroll
        for (int o = 16; o > 0; o >>= 1) {
            unsigned long long oth = __shfl_xor_sync(0xffffffffu, best, o);
            if (oth < best) best = oth;
        }
        if (lane == 0) wmin[warp] = best;
        __syncthreads();
        if (t < 32) {
            unsigned long long v = (t < 8) ? wmin[t] : ~0ull;
            #pragma unroll
            for (int o = 4; o > 0; o >>= 1) {
                unsigned long long oth = __shfl_xor_sync(0xffffffffu, v, o);
                if (oth < v) v = oth;
            }
            if (t == 0) {
                sBest = v;
                int jm = (int)(unsigned)v;
                g_Eidx[row*KNB + it] = jm;
                g_Dsel[row*KNB + it] = __uint_as_float((unsigned)(v >> 32));
                if (outIdxF) outIdxF[row*KNB + it] = (float)jm;
            }
        }
        __syncthreads();
        unsigned long long g = sBest;
        #pragma unroll
        for (int r = 0; r < 8; r++) if (key[r] == g) key[r] = ~0ull;
    }
}

// ============================================================
// Kernel 3: fused edge features (positional + 16 RBF banks)
//           -> 272x128 projection (packed f32x2 FMA) -> layernorm
// One block per (b,i) row; 128 threads = one output column each,
// 15 packed acc pairs cover the 30 neighbors.
// Feature tile stored TRANSPOSED: Fsm[channel][neighbor], 128B row
// stride, so one broadcast LDS.128 feeds 2 packed FMAs.
// W loads are batched 4-wide (MLP=4) ahead of all consumers so the
// L2-latency of W_edge (doesn't fit the smem-carved L1) is hidden.
// ============================================================
__global__ __launch_bounds__(128, 4) void edge_kernel(
    const float* __restrict__ X,
    const int*   __restrict__ ridx,
    const int*   __restrict__ chain,
    const float* __restrict__ W_pos,
    const float* __restrict__ b_pos,
    const float* __restrict__ W_edge,
    const float* __restrict__ gamma,
    const float* __restrict__ beta,
    float*       __restrict__ outE)
{
    int row = blockIdx.x;           // b*L + i
    int b   = row / LSZ;
    int t   = threadIdx.x;

    __shared__ __align__(16) float Fsm[NF][KPAD];   // 272 x 32 (cols 30..31 unused)
    __shared__ float ia[4][3];            // i atoms: N,C,Ca,Cb
    __shared__ float ja[KNB][4][3];       // j atoms per neighbor
    __shared__ int   jidx[KNB];
    __shared__ float dsel[KNB];
    __shared__ float dist[KNB][15];
    __shared__ float psum[4][KNB];
    __shared__ float psq [4][KNB];

    // stage neighbor list + i atoms
    if (t < KNB) { jidx[t] = g_Eidx[row*KNB + t]; dsel[t] = g_Dsel[row*KNB + t]; }
    if (t >= 32 && t < 41) { int r = t - 32; ia[r/3][r%3] = X[row*12 + r]; }
    if (t >= 64 && t < 67) { ia[3][t-64] = g_Cb[row*3 + (t-64)]; }
    __syncthreads();

    // stage j atoms (N,C,Ca from X; Cb virtual)
    for (int s = t; s < KNB*12; s += 128) {
        int k = s / 12, r = s % 12;
        int j = jidx[k];
        if (r < 9) ja[k][r/3][r%3] = X[(b*LSZ + j)*12 + r];
        else       ja[k][3][r-9]   = g_Cb[(b*LSZ + j)*3 + (r-9)];
    }

    // positional features: Fsm[f][k] = W_pos[d] + b_pos  (channels 0..15)
    int my_ri = ridx[row];
    int my_ch = chain[row];
    for (int s = t; s < KNB*16; s += 128) {
        int k = s >> 4, f = s & 15;
        int j = jidx[k];
        int off  = my_ri - ridx[b*LSZ + j];
        int same = (my_ch == chain[b*LSZ + j]);
        int dcode = same ? min(max(off + MAXREL, 0), 2*MAXREL) : (2*MAXREL + 1);
        Fsm[f][k] = W_pos[dcode*16 + f] + b_pos[f];
    }
    __syncthreads();

    // 15 pair distances per edge
    for (int s = t; s < KNB*16; s += 128) {
        int k = s >> 4, p = s & 15;
        if (p < 15) {
            int a = c_PA[p], bb = c_PB[p];
            float dx = ia[a][0] - ja[k][bb][0];
            float dy = ia[a][1] - ja[k][bb][1];
            float dz = ia[a][2] - ja[k][bb][2];
            dist[k][p] = sqrtf(dx*dx + dy*dy + dz*dz + 1e-6f);
        }
    }
    __syncthreads();

    // 16 RBF banks x 16 mus: channel 16 + p*16 + m, transposed write
    for (int s = t; s < KNB*256; s += 128) {
        int k = s >> 8, r = s & 255, p = r >> 4, m = r & 15;
        float d  = (p == 0) ? dsel[k] : dist[k][p-1];
        float mu = 2.0f + (float)m * (20.0f/15.0f);
        float z  = (d - mu) * 0.8f;          // 1/sigma = 16/20
        Fsm[16 + r][k] = __expf(-z*z);
    }
    __syncthreads();

    // ---- GEMM: acc[k] = sum_c Fsm[c][k] * W_edge[c][t], packed pairs ----
    unsigned long long acc2[15];
    #pragma unroll
    for (int p = 0; p < 15; p++) acc2[p] = 0ull;   // (+0.0f, +0.0f)

    const float* Wcol = W_edge + t;
    for (int c = 0; c < NF; c += 4) {
        // batch all 4 W loads first (independent, MLP=4 hides L2 latency)
        float w0 = Wcol[(c+0)*NOUT];
        float w1 = Wcol[(c+1)*NOUT];
        float w2 = Wcol[(c+2)*NOUT];
        float w3 = Wcol[(c+3)*NOUT];
        unsigned long long wp[4];
        wp[0] = pack_dup(w0); wp[1] = pack_dup(w1);
        wp[2] = pack_dup(w2); wp[3] = pack_dup(w3);
        #pragma unroll
        for (int cc = 0; cc < 4; cc++) {
            const float* frow = &Fsm[c + cc][0];
            unsigned long long w = wp[cc];
            #pragma unroll
            for (int q = 0; q < 7; q++) {             // pairs 0..13 via LDS.128
                ulonglong2 fv = *reinterpret_cast<const ulonglong2*>(frow + 4*q);
                ffma2(acc2[2*q  ], fv.x, w);
                ffma2(acc2[2*q+1], fv.y, w);
            }
            unsigned long long ft =                    // pair 14 via LDS.64
                *reinterpret_cast<const unsigned long long*>(frow + 28);
            ffma2(acc2[14], ft, w);
        }
    }

    float acc[KNB];
    #pragma unroll
    for (int p = 0; p < 15; p++) unpack2(acc2[p], acc[2*p], acc[2*p+1]);

    // ---- layernorm over the 128 columns (one element per thread) ----
    int warp = t >> 5, lane = t & 31;
    #pragma unroll
    for (int k = 0; k < KNB; k++) {
        float s = acc[k], q = acc[k]*acc[k];
        #pragma unroll
        for (int o = 16; o > 0; o >>= 1) {
            s += __shfl_xor_sync(0xffffffffu, s, o);
            q += __shfl_xor_sync(0xffffffffu, q, o);
        }
        if (lane == 0) { psum[warp][k] = s; psq[warp][k] = q; }
    }
    __syncthreads();

    float g  = gamma[t];
    float be = beta[t];
    #pragma unroll
    for (int k = 0; k < KNB; k++) {
        float s  = psum[0][k] + psum[1][k] + psum[2][k] + psum[3][k];
        float q  = psq [0][k] + psq [1][k] + psq [2][k] + psq [3][k];
        float mu  = s * (1.0f/NOUT);
        float var = fmaxf(q * (1.0f/NOUT) - mu*mu, 0.0f);
        float inv = rsqrtf(var + 1e-5f);
        outE[(row*KNB + k)*NOUT + t] = (acc[k] - mu)*inv*g + be;
    }
}

// ============================================================
extern "C" void kernel_launch(void* const* d_in, const int* in_sizes, int n_in,
                              void* d_out, int out_size)
{
    const float* X      = (const float*)d_in[0];
    const float* mask   = (const float*)d_in[1];
    const int*   ridx   = (const int*)  d_in[2];
    const int*   chain  = (const int*)  d_in[3];
    const float* W_pos  = (const float*)d_in[4];
    const float* b_pos  = (const float*)d_in[5];
    const float* W_edge = (const float*)d_in[6];
    const float* gamma  = (const float*)d_in[7];
    const float* beta   = (const float*)d_in[8];

    float* outE = (float*)d_out;
    long long esz = (long long)BSZ*LSZ*KNB*NOUT;     // 31,457,280
    // tuple output (E, E_idx): E_idx follows E, cast to the output dtype (f32)
    float* outIdxF = ((long long)out_size > esz) ? (outE + esz) : nullptr;

    cb_kernel  <<<(BSZ*LSZ + 255)/256, 256>>>(X);
    topk_kernel<<<BSZ*LSZ, 256>>>(X, mask, outIdxF);
    edge_kernel<<<BSZ*LSZ, 128>>>(X, ridx, chain, W_pos, b_pos, W_edge,
                                  gamma, beta, outE);
}

// round 8
// speedup vs baseline: 1.2941x; 1.2941x over previous
#include <cuda_runtime.h>
#include <cuda_bf16.h>
#include <cstdint>

// Problem constants (shapes fixed by setup_inputs)
#define BSZ   4
#define LSZ   2048
#define KNB   30      // TOP_K
#define NRBF  16
#define NRB   256     // 16 banks * 16 rbf channels (positional handled via table)
#define NOUT  128
#define MAXREL 32
#define NDC   66      // dcode values: 0..64 same-chain, 65 cross-chain

// -------- device scratch (no cudaMalloc allowed) --------
__device__ float g_Cb  [BSZ*LSZ*3];
__device__ int   g_Eidx[BSZ*LSZ*KNB];
__device__ float g_Dsel[BSZ*LSZ*KNB];
__device__ float g_Tpos[NDC*NOUT];     // (W_pos[d]+b_pos) @ W_edge[0:16]

// pair tables: dist(A_atom of residue i, B_atom of residue j)
// atom codes: 0=N (X[...,0]), 1=C (X[...,1]), 2=Ca (X[...,2]), 3=Cb (virtual)
__constant__ int c_PA[15] = {0,2,3,1,1,1,0,0,3,0,2,3,2,3,2};
__constant__ int c_PB[15] = {0,2,3,0,2,3,2,3,2,1,1,1,0,0,3};

// ============================================================
// Kernel 0: positional projection table
// T[d][t] = sum_f (W_pos[d][f] + b_pos[f]) * W_edge[f][t]
// Same fmaf chain order as an in-GEMM accumulation over c=0..15.
// ============================================================
__global__ void tpos_kernel(const float* __restrict__ W_pos,
                            const float* __restrict__ b_pos,
                            const float* __restrict__ W_edge)
{
    int d = blockIdx.x;        // 0..65
    int t = threadIdx.x;       // 0..127
    float acc = 0.f;
    #pragma unroll
    for (int f = 0; f < 16; f++)
        acc = fmaf(W_pos[d*16 + f] + b_pos[f], W_edge[f*NOUT + t], acc);
    g_Tpos[d*NOUT + t] = acc;
}

// ============================================================
// Kernel 1: virtual C-beta per residue
// ============================================================
__global__ void cb_kernel(const float* __restrict__ X)
{
    int i = blockIdx.x * 256 + threadIdx.x;
    if (i >= BSZ*LSZ) return;
    const float* x = &X[i*12];
    float Nx=x[0],  Ny=x[1],  Nz=x[2];   // N  = X[:,:,0]
    float Cx=x[3],  Cy=x[4],  Cz=x[5];   // C  = X[:,:,1]
    float Ax=x[6],  Ay=x[7],  Az=x[8];   // Ca = X[:,:,2]
    float bx=Ax-Nx, by=Ay-Ny, bz=Az-Nz;          // b = Ca - N
    float cx=Cx-Ax, cy=Cy-Ay, cz=Cz-Az;          // c = C - Ca
    float ax = by*cz - bz*cy;                    // a = cross(b,c)
    float ay = bz*cx - bx*cz;
    float az = bx*cy - by*cx;
    g_Cb[i*3+0] = -0.58273431f*ax + 0.56802827f*bx - 0.54067466f*cx + Ax;
    g_Cb[i*3+1] = -0.58273431f*ay + 0.56802827f*by - 0.54067466f*cy + Ay;
    g_Cb[i*3+2] = -0.58273431f*az + 0.56802827f*bz - 0.54067466f*cz + Az;
}

// ============================================================
// Kernel 2: masked pairwise C-C distances + exact top-30
// Keys in REGISTERS: key = (float_bits << 32) | j  -> min gives
// ascending distance, ties to lower index (jax.lax.top_k order).
// Incremental rounds: per-warp minima live in double-buffered smem;
// after each extraction only the OWNING warp re-reduces its keys.
// One __syncthreads per round.
// ============================================================
__global__ __launch_bounds__(256) void topk_kernel(
    const float* __restrict__ X, const float* __restrict__ mask,
    float* __restrict__ outIdxF)
{
    int row = blockIdx.x;           // b*L + i
    int b   = row / LSZ;
    int t   = threadIdx.x;
    int warp = t >> 5, lane = t & 31;

    __shared__ float wmax[8];
    __shared__ float sDmax;
    __shared__ unsigned long long buf[2][8];   // double-buffered per-warp minima

    float cx = X[row*12+3], cy = X[row*12+4], cz = X[row*12+5];  // C atom
    float mi = mask[row];

    float dv[8], m2v[8];
    float lmax = 0.f;
    #pragma unroll
    for (int r = 0; r < 8; r++) {
        int j = t + r*256;
        const float* xj = &X[(b*LSZ + j)*12 + 3];
        float dx = cx-xj[0], dy = cy-xj[1], dz = cz-xj[2];
        float d  = sqrtf(dx*dx + dy*dy + dz*dz + 1e-6f);
        float m2 = mi * mask[b*LSZ + j];
        float md = m2 * d;
        dv[r]  = md;
        m2v[r] = m2;
        lmax = fmaxf(lmax, md);
    }
    #pragma unroll
    for (int o = 16; o > 0; o >>= 1) lmax = fmaxf(lmax, __shfl_xor_sync(0xffffffffu, lmax, o));
    if (lane == 0) wmax[warp] = lmax;
    __syncthreads();
    if (t == 0) {
        float m = wmax[0];
        for (int w = 1; w < 8; w++) m = fmaxf(m, wmax[w]);
        sDmax = m;
    }
    __syncthreads();
    float Dmax = sDmax;

    unsigned long long key[8];
    #pragma unroll
    for (int r = 0; r < 8; r++) {
        float adj = dv[r] + (1.0f - m2v[r]) * Dmax;      // D_adjust
        key[r] = ((unsigned long long)__float_as_uint(adj) << 32)
               | (unsigned)(t + r*256);
    }

    // initial per-warp minimum -> buf[0]
    {
        unsigned long long best = key[0];
        #pragma unroll
        for (int r = 1; r < 8; r++) if (key[r] < best) best = key[r];
        #pragma unroll
        for (int o = 16; o > 0; o >>= 1) {
            unsigned long long oth = __shfl_xor_sync(0xffffffffu, best, o);
            if (oth < best) best = oth;
        }
        if (lane == 0) buf[0][warp] = best;
    }
    __syncthreads();

    #pragma unroll 1
    for (int it = 0; it < KNB; it++) {
        const unsigned long long* rd = buf[it & 1];
        unsigned long long*       wr = buf[(it + 1) & 1];

        unsigned long long mymin = rd[warp];
        unsigned long long g = rd[0];
        #pragma unroll
        for (int w = 1; w < 8; w++) { unsigned long long v = rd[w]; if (v < g) g = v; }

        if (t == 0) {
            int jm = (int)(unsigned)g;
            g_Eidx[row*KNB + it] = jm;
            g_Dsel[row*KNB + it] = __uint_as_float((unsigned)(g >> 32));
            if (outIdxF) outIdxF[row*KNB + it] = (float)jm;
        }

        if (mymin == g) {
            // owning warp: remove the winner, re-reduce its 256 keys
            #pragma unroll
            for (int r = 0; r < 8; r++) if (key[r] == g) key[r] = ~0ull;
            unsigned long long best = key[0];
            #pragma unroll
            for (int r = 1; r < 8; r++) if (key[r] < best) best = key[r];
            #pragma unroll
            for (int o = 16; o > 0; o >>= 1) {
                unsigned long long oth = __shfl_xor_sync(0xffffffffu, best, o);
                if (oth < best) best = oth;
            }
            if (lane == 0) wr[warp] = best;
        } else {
            if (lane == 0) wr[warp] = mymin;
        }
        __syncthreads();
    }
}

// ============================================================
// Kernel 3: fused edge features (16 RBF banks) -> 256x128
// projection (scalar fmaf, W loads batched 4-wide) + positional
// table init -> layernorm.
// One block per (b,i) row; 128 threads = one output column each,
// acc[30] register tile over the 30 neighbors.
// ============================================================
__global__ __launch_bounds__(128, 4) void edge_kernel(
    const float* __restrict__ X,
    const int*   __restrict__ ridx,
    const int*   __restrict__ chain,
    const float* __restrict__ W_edge,
    const float* __restrict__ gamma,
    const float* __restrict__ beta,
    float*       __restrict__ outE)
{
    int row = blockIdx.x;           // b*L + i
    int b   = row / LSZ;
    int t   = threadIdx.x;

    __shared__ __align__(16) float Fsm[KNB][NRB];   // 30 x 256 RBF features
    __shared__ float ia[4][3];            // i atoms: N,C,Ca,Cb
    __shared__ float ja[KNB][4][3];       // j atoms per neighbor
    __shared__ int   jidx[KNB];
    __shared__ int   sdc [KNB];           // dcode per neighbor
    __shared__ float dsel[KNB];
    __shared__ float dist[KNB][15];
    __shared__ float psum[4][KNB];
    __shared__ float psq [4][KNB];

    // stage neighbor list + i atoms
    if (t < KNB) { jidx[t] = g_Eidx[row*KNB + t]; dsel[t] = g_Dsel[row*KNB + t]; }
    if (t >= 32 && t < 41) { int r = t - 32; ia[r/3][r%3] = X[row*12 + r]; }
    if (t >= 64 && t < 67) { ia[3][t-64] = g_Cb[row*3 + (t-64)]; }
    __syncthreads();

    // stage j atoms (N,C,Ca from X; Cb virtual)
    for (int s = t; s < KNB*12; s += 128) {
        int k = s / 12, r = s % 12;
        int j = jidx[k];
        if (r < 9) ja[k][r/3][r%3] = X[(b*LSZ + j)*12 + r];
        else       ja[k][3][r-9]   = g_Cb[(b*LSZ + j)*3 + (r-9)];
    }

    // dcode per neighbor (positional table row index)
    if (t < KNB) {
        int j = jidx[t];
        int off  = ridx[row] - ridx[b*LSZ + j];
        int same = (chain[row] == chain[b*LSZ + j]);
        sdc[t] = same ? min(max(off + MAXREL, 0), 2*MAXREL) : (2*MAXREL + 1);
    }
    __syncthreads();

    // 15 pair distances per edge
    for (int s = t; s < KNB*16; s += 128) {
        int k = s >> 4, p = s & 15;
        if (p < 15) {
            int a = c_PA[p], bb = c_PB[p];
            float dx = ia[a][0] - ja[k][bb][0];
            float dy = ia[a][1] - ja[k][bb][1];
            float dz = ia[a][2] - ja[k][bb][2];
            dist[k][p] = sqrtf(dx*dx + dy*dy + dz*dz + 1e-6f);
        }
    }
    __syncthreads();

    // 16 RBF banks x 16 mus: Fsm[k][p*16 + m]
    for (int s = t; s < KNB*256; s += 128) {
        int k = s >> 8, r = s & 255, p = r >> 4, m = r & 15;
        float d  = (p == 0) ? dsel[k] : dist[k][p-1];
        float mu = 2.0f + (float)m * (20.0f/15.0f);
        float z  = (d - mu) * 0.8f;          // 1/sigma = 16/20
        Fsm[k][r] = __expf(-z*z);
    }
    __syncthreads();

    // ---- acc init from positional table; then GEMM over 256 RBF ----
    float acc[KNB];
    #pragma unroll
    for (int k = 0; k < KNB; k++) acc[k] = g_Tpos[sdc[k]*NOUT + t];

    const float* Wcol = W_edge + 16*NOUT + t;   // skip 16 positional rows
    for (int c = 0; c < NRB; c += 4) {
        float w0 = Wcol[(c+0)*NOUT];
        float w1 = Wcol[(c+1)*NOUT];
        float w2 = Wcol[(c+2)*NOUT];
        float w3 = Wcol[(c+3)*NOUT];
        #pragma unroll
        for (int k = 0; k < KNB; k++) {
            float4 f = *reinterpret_cast<const float4*>(&Fsm[k][c]);
            acc[k] = fmaf(f.x, w0, acc[k]);
            acc[k] = fmaf(f.y, w1, acc[k]);
            acc[k] = fmaf(f.z, w2, acc[k]);
            acc[k] = fmaf(f.w, w3, acc[k]);
        }
    }

    // ---- layernorm over the 128 columns (one element per thread) ----
    int warp = t >> 5, lane = t & 31;
    #pragma unroll
    for (int k = 0; k < KNB; k++) {
        float s = acc[k], q = acc[k]*acc[k];
        #pragma unroll
        for (int o = 16; o > 0; o >>= 1) {
            s += __shfl_xor_sync(0xffffffffu, s, o);
            q += __shfl_xor_sync(0xffffffffu, q, o);
        }
        if (lane == 0) { psum[warp][k] = s; psq[warp][k] = q; }
    }
    __syncthreads();

    float g  = gamma[t];
    float be = beta[t];
    #pragma unroll
    for (int k = 0; k < KNB; k++) {
        float s  = psum[0][k] + psum[1][k] + psum[2][k] + psum[3][k];
        float q  = psq [0][k] + psq [1][k] + psq [2][k] + psq [3][k];
        float mu  = s * (1.0f/NOUT);
        float var = fmaxf(q * (1.0f/NOUT) - mu*mu, 0.0f);
        float inv = rsqrtf(var + 1e-5f);
        outE[(row*KNB + k)*NOUT + t] = (acc[k] - mu)*inv*g + be;
    }
}

// ============================================================
extern "C" void kernel_launch(void* const* d_in, const int* in_sizes, int n_in,
                              void* d_out, int out_size)
{
    const float* X      = (const float*)d_in[0];
    const float* mask   = (const float*)d_in[1];
    const int*   ridx   = (const int*)  d_in[2];
    const int*   chain  = (const int*)  d_in[3];
    const float* W_pos  = (const float*)d_in[4];
    const float* b_pos  = (const float*)d_in[5];
    const float* W_edge = (const float*)d_in[6];
    const float* gamma  = (const float*)d_in[7];
    const float* beta   = (const float*)d_in[8];

    float* outE = (float*)d_out;
    long long esz = (long long)BSZ*LSZ*KNB*NOUT;     // 31,457,280
    // tuple output (E, E_idx): E_idx follows E, cast to the output dtype (f32)
    float* outIdxF = ((long long)out_size > esz) ? (outE + esz) : nullptr;

    tpos_kernel<<<NDC, NOUT>>>(W_pos, b_pos, W_edge);
    cb_kernel  <<<(BSZ*LSZ + 255)/256, 256>>>(X);
    topk_kernel<<<BSZ*LSZ, 256>>>(X, mask, outIdxF);
    edge_kernel<<<BSZ*LSZ, 128>>>(X, ridx, chain, W_edge, gamma, beta, outE);
}

// round 9
// speedup vs baseline: 1.5119x; 1.1683x over previous
#include <cuda_runtime.h>
#include <cuda_bf16.h>
#include <cstdint>

// Problem constants (shapes fixed by setup_inputs)
#define BSZ   4
#define LSZ   2048
#define KNB   30      // TOP_K
#define KH    15      // neighbors per thread-half
#define NRBF  16
#define NRB   256     // 16 banks * 16 rbf channels (positional handled via table)
#define NOUT  128
#define MAXREL 32
#define NDC   66      // dcode values: 0..64 same-chain, 65 cross-chain

// -------- device scratch (no cudaMalloc allowed) --------
__device__ float g_Cb  [BSZ*LSZ*3];
__device__ int   g_Eidx[BSZ*LSZ*KNB];
__device__ float g_Dsel[BSZ*LSZ*KNB];
__device__ float g_Tpos[NDC*NOUT];     // (W_pos[d]+b_pos) @ W_edge[0:16]

// pair tables: dist(A_atom of residue i, B_atom of residue j)
// atom codes: 0=N (X[...,0]), 1=C (X[...,1]), 2=Ca (X[...,2]), 3=Cb (virtual)
__constant__ int c_PA[15] = {0,2,3,1,1,1,0,0,3,0,2,3,2,3,2};
__constant__ int c_PB[15] = {0,2,3,0,2,3,2,3,2,1,1,1,0,0,3};

// ============================================================
// Kernel 0: positional projection table
// T[d][t] = sum_f (W_pos[d][f] + b_pos[f]) * W_edge[f][t]
// ============================================================
__global__ void tpos_kernel(const float* __restrict__ W_pos,
                            const float* __restrict__ b_pos,
                            const float* __restrict__ W_edge)
{
    int d = blockIdx.x;        // 0..65
    int t = threadIdx.x;       // 0..127
    float acc = 0.f;
    #pragma unroll
    for (int f = 0; f < 16; f++)
        acc = fmaf(W_pos[d*16 + f] + b_pos[f], W_edge[f*NOUT + t], acc);
    g_Tpos[d*NOUT + t] = acc;
}

// ============================================================
// Kernel 1: virtual C-beta per residue
// ============================================================
__global__ void cb_kernel(const float* __restrict__ X)
{
    int i = blockIdx.x * 256 + threadIdx.x;
    if (i >= BSZ*LSZ) return;
    const float* x = &X[i*12];
    float Nx=x[0],  Ny=x[1],  Nz=x[2];   // N  = X[:,:,0]
    float Cx=x[3],  Cy=x[4],  Cz=x[5];   // C  = X[:,:,1]
    float Ax=x[6],  Ay=x[7],  Az=x[8];   // Ca = X[:,:,2]
    float bx=Ax-Nx, by=Ay-Ny, bz=Az-Nz;          // b = Ca - N
    float cx=Cx-Ax, cy=Cy-Ay, cz=Cz-Az;          // c = C - Ca
    float ax = by*cz - bz*cy;                    // a = cross(b,c)
    float ay = bz*cx - bx*cz;
    float az = bx*cy - by*cx;
    g_Cb[i*3+0] = -0.58273431f*ax + 0.56802827f*bx - 0.54067466f*cx + Ax;
    g_Cb[i*3+1] = -0.58273431f*ay + 0.56802827f*by - 0.54067466f*cy + Ay;
    g_Cb[i*3+2] = -0.58273431f*az + 0.56802827f*bz - 0.54067466f*cz + Az;
}

// ============================================================
// Kernel 2: masked pairwise C-C distances + exact top-30
// Keys in REGISTERS: key = (float_bits << 32) | j  -> min gives
// ascending distance, ties to lower index (jax.lax.top_k order).
// Incremental rounds: per-warp minima in double-buffered smem;
// after each extraction only the OWNING warp re-reduces.
// ============================================================
__global__ __launch_bounds__(256) void topk_kernel(
    const float* __restrict__ X, const float* __restrict__ mask,
    float* __restrict__ outIdxF)
{
    int row = blockIdx.x;           // b*L + i
    int b   = row / LSZ;
    int t   = threadIdx.x;
    int warp = t >> 5, lane = t & 31;

    __shared__ float wmax[8];
    __shared__ float sDmax;
    __shared__ unsigned long long buf[2][8];   // double-buffered per-warp minima

    float cx = X[row*12+3], cy = X[row*12+4], cz = X[row*12+5];  // C atom
    float mi = mask[row];

    float dv[8], m2v[8];
    float lmax = 0.f;
    #pragma unroll
    for (int r = 0; r < 8; r++) {
        int j = t + r*256;
        const float* xj = &X[(b*LSZ + j)*12 + 3];
        float dx = cx-xj[0], dy = cy-xj[1], dz = cz-xj[2];
        float d  = sqrtf(dx*dx + dy*dy + dz*dz + 1e-6f);
        float m2 = mi * mask[b*LSZ + j];
        float md = m2 * d;
        dv[r]  = md;
        m2v[r] = m2;
        lmax = fmaxf(lmax, md);
    }
    #pragma unroll
    for (int o = 16; o > 0; o >>= 1) lmax = fmaxf(lmax, __shfl_xor_sync(0xffffffffu, lmax, o));
    if (lane == 0) wmax[warp] = lmax;
    __syncthreads();
    if (t == 0) {
        float m = wmax[0];
        for (int w = 1; w < 8; w++) m = fmaxf(m, wmax[w]);
        sDmax = m;
    }
    __syncthreads();
    float Dmax = sDmax;

    unsigned long long key[8];
    #pragma unroll
    for (int r = 0; r < 8; r++) {
        float adj = dv[r] + (1.0f - m2v[r]) * Dmax;      // D_adjust
        key[r] = ((unsigned long long)__float_as_uint(adj) << 32)
               | (unsigned)(t + r*256);
    }

    // initial per-warp minimum -> buf[0]
    {
        unsigned long long best = key[0];
        #pragma unroll
        for (int r = 1; r < 8; r++) if (key[r] < best) best = key[r];
        #pragma unroll
        for (int o = 16; o > 0; o >>= 1) {
            unsigned long long oth = __shfl_xor_sync(0xffffffffu, best, o);
            if (oth < best) best = oth;
        }
        if (lane == 0) buf[0][warp] = best;
    }
    __syncthreads();

    #pragma unroll 1
    for (int it = 0; it < KNB; it++) {
        const unsigned long long* rd = buf[it & 1];
        unsigned long long*       wr = buf[(it + 1) & 1];

        unsigned long long mymin = rd[warp];
        unsigned long long g = rd[0];
        #pragma unroll
        for (int w = 1; w < 8; w++) { unsigned long long v = rd[w]; if (v < g) g = v; }

        if (t == 0) {
            int jm = (int)(unsigned)g;
            g_Eidx[row*KNB + it] = jm;
            g_Dsel[row*KNB + it] = __uint_as_float((unsigned)(g >> 32));
            if (outIdxF) outIdxF[row*KNB + it] = (float)jm;
        }

        if (mymin == g) {
            #pragma unroll
            for (int r = 0; r < 8; r++) if (key[r] == g) key[r] = ~0ull;
            unsigned long long best = key[0];
            #pragma unroll
            for (int r = 1; r < 8; r++) if (key[r] < best) best = key[r];
            #pragma unroll
            for (int o = 16; o > 0; o >>= 1) {
                unsigned long long oth = __shfl_xor_sync(0xffffffffu, best, o);
                if (oth < best) best = oth;
            }
            if (lane == 0) wr[warp] = best;
        } else {
            if (lane == 0) wr[warp] = mymin;
        }
        __syncthreads();
    }
}

// ============================================================
// Kernel 3: fused edge features (16 RBF banks) -> 256x128
// projection + positional table init -> layernorm.
// TILING: thread t -> half = t>>6 (k in [15h, 15h+15)), and
// column pair (2*(t&63), 2*(t&63)+1). Halves the broadcast-LDS
// stream (the ncu-measured bottleneck: L1=84%) at the cost of
// 2-wide W LDG.64, net ~0.68x L1 wavefronts.
// Layernorm per k needs exactly warps {2h, 2h+1}.
// ============================================================
__global__ __launch_bounds__(128, 4) void edge_kernel(
    const float* __restrict__ X,
    const int*   __restrict__ ridx,
    const int*   __restrict__ chain,
    const float* __restrict__ W_edge,
    const float* __restrict__ gamma,
    const float* __restrict__ beta,
    float*       __restrict__ outE)
{
    int row = blockIdx.x;           // b*L + i
    int b   = row / LSZ;
    int t   = threadIdx.x;
    int half = t >> 6;              // which 15 neighbors
    int cl   = t & 63;              // column pair index

    __shared__ __align__(16) float Fsm[KNB][NRB];   // 30 x 256 RBF features
    __shared__ float ia[4][3];            // i atoms: N,C,Ca,Cb
    __shared__ float ja[KNB][4][3];       // j atoms per neighbor
    __shared__ int   jidx[KNB];
    __shared__ int   sdc [KNB];           // dcode per neighbor
    __shared__ float dsel[KNB];
    __shared__ float dist[KNB][15];
    __shared__ float psum[4][KH];
    __shared__ float psq [4][KH];

    // stage neighbor list + i atoms
    if (t < KNB) { jidx[t] = g_Eidx[row*KNB + t]; dsel[t] = g_Dsel[row*KNB + t]; }
    if (t >= 32 && t < 41) { int r = t - 32; ia[r/3][r%3] = X[row*12 + r]; }
    if (t >= 64 && t < 67) { ia[3][t-64] = g_Cb[row*3 + (t-64)]; }
    __syncthreads();

    // stage j atoms (N,C,Ca from X; Cb virtual)
    for (int s = t; s < KNB*12; s += 128) {
        int k = s / 12, r = s % 12;
        int j = jidx[k];
        if (r < 9) ja[k][r/3][r%3] = X[(b*LSZ + j)*12 + r];
        else       ja[k][3][r-9]   = g_Cb[(b*LSZ + j)*3 + (r-9)];
    }

    // dcode per neighbor (positional table row index)
    if (t < KNB) {
        int j = jidx[t];
        int off  = ridx[row] - ridx[b*LSZ + j];
        int same = (chain[row] == chain[b*LSZ + j]);
        sdc[t] = same ? min(max(off + MAXREL, 0), 2*MAXREL) : (2*MAXREL + 1);
    }
    __syncthreads();

    // 15 pair distances per edge
    for (int s = t; s < KNB*16; s += 128) {
        int k = s >> 4, p = s & 15;
        if (p < 15) {
            int a = c_PA[p], bb = c_PB[p];
            float dx = ia[a][0] - ja[k][bb][0];
            float dy = ia[a][1] - ja[k][bb][1];
            float dz = ia[a][2] - ja[k][bb][2];
            dist[k][p] = sqrtf(dx*dx + dy*dy + dz*dz + 1e-6f);
        }
    }
    __syncthreads();

    // 16 RBF banks x 16 mus: Fsm[k][p*16 + m]
    for (int s = t; s < KNB*256; s += 128) {
        int k = s >> 8, r = s & 255, p = r >> 4, m = r & 15;
        float d  = (p == 0) ? dsel[k] : dist[k][p-1];
        float mu = 2.0f + (float)m * (20.0f/15.0f);
        float z  = (d - mu) * 0.8f;          // 1/sigma = 16/20
        Fsm[k][r] = __expf(-z*z);
    }
    __syncthreads();

    // ---- acc init from positional table; GEMM over 256 RBF channels ----
    float acc0[KH], acc1[KH];
    #pragma unroll
    for (int kk = 0; kk < KH; kk++) {
        float2 tp = *reinterpret_cast<const float2*>(
            &g_Tpos[sdc[half*KH + kk]*NOUT + 2*cl]);
        acc0[kk] = tp.x; acc1[kk] = tp.y;
    }

    const float* Wb = W_edge + 16*NOUT + 2*cl;   // skip 16 positional rows
    const float (*Fh)[NRB] = &Fsm[half*KH];
    for (int c = 0; c < NRB; c += 4) {
        // batch 4 independent W loads (MLP=4 hides L2 latency)
        float2 w0 = *reinterpret_cast<const float2*>(&Wb[(c+0)*NOUT]);
        float2 w1 = *reinterpret_cast<const float2*>(&Wb[(c+1)*NOUT]);
        float2 w2 = *reinterpret_cast<const float2*>(&Wb[(c+2)*NOUT]);
        float2 w3 = *reinterpret_cast<const float2*>(&Wb[(c+3)*NOUT]);
        #pragma unroll
        for (int kk = 0; kk < KH; kk++) {
            float4 f = *reinterpret_cast<const float4*>(&Fh[kk][c]);
            acc0[kk] = fmaf(f.x, w0.x, acc0[kk]);
            acc1[kk] = fmaf(f.x, w0.y, acc1[kk]);
            acc0[kk] = fmaf(f.y, w1.x, acc0[kk]);
            acc1[kk] = fmaf(f.y, w1.y, acc1[kk]);
            acc0[kk] = fmaf(f.z, w2.x, acc0[kk]);
            acc1[kk] = fmaf(f.z, w2.y, acc1[kk]);
            acc0[kk] = fmaf(f.w, w3.x, acc0[kk]);
            acc1[kk] = fmaf(f.w, w3.y, acc1[kk]);
        }
    }

    // ---- layernorm: k's 128 cols live in warps {2*half, 2*half+1} ----
    int warp = t >> 5, lane = t & 31;
    #pragma unroll
    for (int kk = 0; kk < KH; kk++) {
        float s = acc0[kk] + acc1[kk];
        float q = acc0[kk]*acc0[kk] + acc1[kk]*acc1[kk];
        #pragma unroll
        for (int o = 16; o > 0; o >>= 1) {
            s += __shfl_xor_sync(0xffffffffu, s, o);
            q += __shfl_xor_sync(0xffffffffu, q, o);
        }
        if (lane == 0) { psum[warp][kk] = s; psq[warp][kk] = q; }
    }
    __syncthreads();

    float2 gm = *reinterpret_cast<const float2*>(&gamma[2*cl]);
    float2 bt = *reinterpret_cast<const float2*>(&beta [2*cl]);
    #pragma unroll
    for (int kk = 0; kk < KH; kk++) {
        int k = half*KH + kk;
        float s  = psum[2*half][kk] + psum[2*half+1][kk];
        float q  = psq [2*half][kk] + psq [2*half+1][kk];
        float mu  = s * (1.0f/NOUT);
        float var = fmaxf(q * (1.0f/NOUT) - mu*mu, 0.0f);
        float inv = rsqrtf(var + 1e-5f);
        float2 o;
        o.x = (acc0[kk] - mu)*inv*gm.x + bt.x;
        o.y = (acc1[kk] - mu)*inv*gm.y + bt.y;
        *reinterpret_cast<float2*>(&outE[(row*KNB + k)*NOUT + 2*cl]) = o;
    }
}

// ============================================================
extern "C" void kernel_launch(void* const* d_in, const int* in_sizes, int n_in,
                              void* d_out, int out_size)
{
    const float* X      = (const float*)d_in[0];
    const float* mask   = (const float*)d_in[1];
    const int*   ridx   = (const int*)  d_in[2];
    const int*   chain  = (const int*)  d_in[3];
    const float* W_pos  = (const float*)d_in[4];
    const float* b_pos  = (const float*)d_in[5];
    const float* W_edge = (const float*)d_in[6];
    const float* gamma  = (const float*)d_in[7];
    const float* beta   = (const float*)d_in[8];

    float* outE = (float*)d_out;
    long long esz = (long long)BSZ*LSZ*KNB*NOUT;     // 31,457,280
    // tuple output (E, E_idx): E_idx follows E, cast to the output dtype (f32)
    float* outIdxF = ((long long)out_size > esz) ? (outE + esz) : nullptr;

    tpos_kernel<<<NDC, NOUT>>>(W_pos, b_pos, W_edge);
    cb_kernel  <<<(BSZ*LSZ + 255)/256, 256>>>(X);
    topk_kernel<<<BSZ*LSZ, 256>>>(X, mask, outIdxF);
    edge_kernel<<<BSZ*LSZ, 128>>>(X, ridx, chain, W_edge, gamma, beta, outE);
}

// round 12
// speedup vs baseline: 2.0293x; 1.3422x over previous
#include <cuda_runtime.h>
#include <cuda_bf16.h>
#include <cstdint>

// Problem constants (shapes fixed by setup_inputs)
#define BSZ   4
#define LSZ   2048
#define KNB   30      // TOP_K
#define NRB   256     // 16 banks * 16 rbf channels (positional via table)
#define NOUT  128
#define MAXREL 32
#define NDC   66      // dcode values: 0..64 same-chain, 65 cross-chain
#define NEDGE (BSZ*LSZ*KNB)     // 245760
#define MTILES (NEDGE/128)      // 1920 (exact)
#define ASTRIDE 72              // smem A row stride in bf16 (144B, 16B-aligned)

// -------- device scratch (no cudaMalloc allowed) --------
__device__ float    g_Cb  [BSZ*LSZ*3];
__device__ int      g_Eidx[NEDGE];
__device__ float    g_Dsel[NEDGE];
__device__ int      g_Dcode[NEDGE];
__device__ float    g_Tpos[NDC*NOUT];          // (W_pos[d]+b_pos) @ W_edge[0:16]
__device__ uint32_t g_Fh[(size_t)NEDGE*128];   // features hi, bf16x2 pairs
__device__ uint32_t g_Fl[(size_t)NEDGE*128];   // features lo
__device__ uint2    g_WfH[16*16*32];           // W hi, B-fragment layout [ks][nf][lane]
__device__ uint2    g_WfL[16*16*32];           // W lo

// pair tables: dist(A_atom of residue i, B_atom of residue j)
// atom codes: 0=N, 1=C, 2=Ca, 3=Cb(virtual)
__constant__ int c_PA[15] = {0,2,3,1,1,1,0,0,3,0,2,3,2,3,2};
__constant__ int c_PB[15] = {0,2,3,0,2,3,2,3,2,1,1,1,0,0,3};

// ---------- helpers ----------
__device__ __forceinline__ uint32_t pack_bf16x2(__nv_bfloat16 lo, __nv_bfloat16 hi) {
    uint32_t l = (uint32_t)__bfloat16_as_ushort(lo);
    uint32_t h = (uint32_t)__bfloat16_as_ushort(hi);
    return l | (h << 16);
}
__device__ __forceinline__ uint32_t smem_to_u32(const void* p) {
    uint32_t a;
    asm("{ .reg .u64 t; cvta.to.shared.u64 t, %1; cvt.u32.u64 %0, t; }"
        : "=r"(a) : "l"(p));
    return a;
}
__device__ __forceinline__ void ldsm_x4(uint32_t* r, uint32_t addr) {
    asm volatile("ldmatrix.sync.aligned.m8n8.x4.shared.b16 {%0,%1,%2,%3}, [%4];"
        : "=r"(r[0]), "=r"(r[1]), "=r"(r[2]), "=r"(r[3]) : "r"(addr));
}
__device__ __forceinline__ void mma_bf16(float* c, const uint32_t* a,
                                         const uint32_t* b) {
    asm volatile(
        "mma.sync.aligned.m16n8k16.row.col.f32.bf16.bf16.f32 "
        "{%0,%1,%2,%3}, {%4,%5,%6,%7}, {%8,%9}, {%0,%1,%2,%3};"
        : "+f"(c[0]), "+f"(c[1]), "+f"(c[2]), "+f"(c[3])
        : "r"(a[0]), "r"(a[1]), "r"(a[2]), "r"(a[3]), "r"(b[0]), "r"(b[1]));
}
// exp(-u), u >= 0, FMA/ALU pipes only (no MUFU). ~1e-7 rel.
__device__ __forceinline__ float exp_neg(float u) {
    float t = fmaxf(-u * 1.4426950408889634f, -150.0f);
    float k = rintf(t);
    float f = t - k;
    float p =        1.5403530393e-4f;
    p = fmaf(p, f, 1.3333558146e-3f);
    p = fmaf(p, f, 9.6181291076e-3f);
    p = fmaf(p, f, 5.5504108665e-2f);
    p = fmaf(p, f, 2.4022650696e-1f);
    p = fmaf(p, f, 6.9314718056e-1f);
    p = fmaf(p, f, 1.0f);
    int ki = (int)k;
    int k1 = ki >> 1, k2 = ki - k1;        // two-step scale, no underflow wrap
    float s1 = __int_as_float((k1 + 127) << 23);
    float s2 = __int_as_float((k2 + 127) << 23);
    return p * s1 * s2;
}

// ============================================================
// Kernel 0a: positional projection table
// ============================================================
__global__ void tpos_kernel(const float* __restrict__ W_pos,
                            const float* __restrict__ b_pos,
                            const float* __restrict__ W_edge)
{
    int d = blockIdx.x, t = threadIdx.x;
    float acc = 0.f;
    #pragma unroll
    for (int f = 0; f < 16; f++)
        acc = fmaf(W_pos[d*16 + f] + b_pos[f], W_edge[f*NOUT + t], acc);
    g_Tpos[d*NOUT + t] = acc;
}

// Kernel 0b: W -> bf16 hi/lo in exact mma.sync B-fragment order.
// frag (ks, nfg, lane): n = nfg*8 + (lane>>2); k = ks*16 + 2*(lane&3);
// b0 = (W[k][n], W[k+1][n]); b1 = (W[k+8][n], W[k+9][n])  (k rel. to row 16)
__global__ void wprep_kernel(const float* __restrict__ W_edge)
{
    int idx = blockIdx.x*256 + threadIdx.x;      // 8192 frags
    int lane = idx & 31, nfg = (idx >> 5) & 15, ks = idx >> 9;
    int n = nfg*8 + (lane >> 2);
    int k = ks*16 + 2*(lane & 3);
    float w[4];
    w[0] = W_edge[(16 + k    )*NOUT + n];
    w[1] = W_edge[(16 + k + 1)*NOUT + n];
    w[2] = W_edge[(16 + k + 8)*NOUT + n];
    w[3] = W_edge[(16 + k + 9)*NOUT + n];
    __nv_bfloat16 h[4]; float l[4];
    #pragma unroll
    for (int i = 0; i < 4; i++) {
        h[i] = __float2bfloat16(w[i]);
        l[i] = w[i] - __bfloat162float(h[i]);
    }
    uint2 uh, ul;
    uh.x = pack_bf16x2(h[0], h[1]);
    uh.y = pack_bf16x2(h[2], h[3]);
    ul.x = pack_bf16x2(__float2bfloat16(l[0]), __float2bfloat16(l[1]));
    ul.y = pack_bf16x2(__float2bfloat16(l[2]), __float2bfloat16(l[3]));
    g_WfH[idx] = uh;
    g_WfL[idx] = ul;
}

// ============================================================
// Kernel 1: virtual C-beta per residue
// ============================================================
__global__ void cb_kernel(const float* __restrict__ X)
{
    int i = blockIdx.x * 256 + threadIdx.x;
    if (i >= BSZ*LSZ) return;
    const float* x = &X[i*12];
    float Nx=x[0],  Ny=x[1],  Nz=x[2];
    float Cx=x[3],  Cy=x[4],  Cz=x[5];
    float Ax=x[6],  Ay=x[7],  Az=x[8];
    float bx=Ax-Nx, by=Ay-Ny, bz=Az-Nz;
    float cx=Cx-Ax, cy=Cy-Ay, cz=Cz-Az;
    float ax = by*cz - bz*cy;
    float ay = bz*cx - bx*cz;
    float az = bx*cy - by*cx;
    g_Cb[i*3+0] = -0.58273431f*ax + 0.56802827f*bx - 0.54067466f*cx + Ax;
    g_Cb[i*3+1] = -0.58273431f*ay + 0.56802827f*by - 0.54067466f*cy + Ay;
    g_Cb[i*3+2] = -0.58273431f*az + 0.56802827f*bz - 0.54067466f*cz + Az;
}

// ============================================================
// Kernel 2: masked pairwise C-C distances + exact top-30
// (unchanged from the 703us baseline)
// ============================================================
__global__ __launch_bounds__(256) void topk_kernel(
    const float* __restrict__ X, const float* __restrict__ mask,
    float* __restrict__ outIdxF)
{
    int row = blockIdx.x;
    int b   = row / LSZ;
    int t   = threadIdx.x;
    int warp = t >> 5, lane = t & 31;

    __shared__ float wmax[8];
    __shared__ float sDmax;
    __shared__ unsigned long long buf[2][8];

    float cx = X[row*12+3], cy = X[row*12+4], cz = X[row*12+5];
    float mi = mask[row];

    float dv[8], m2v[8];
    float lmax = 0.f;
    #pragma unroll
    for (int r = 0; r < 8; r++) {
        int j = t + r*256;
        const float* xj = &X[(b*LSZ + j)*12 + 3];
        float dx = cx-xj[0], dy = cy-xj[1], dz = cz-xj[2];
        float d  = sqrtf(dx*dx + dy*dy + dz*dz + 1e-6f);
        float m2 = mi * mask[b*LSZ + j];
        float md = m2 * d;
        dv[r]  = md;
        m2v[r] = m2;
        lmax = fmaxf(lmax, md);
    }
    #pragma unroll
    for (int o = 16; o > 0; o >>= 1) lmax = fmaxf(lmax, __shfl_xor_sync(0xffffffffu, lmax, o));
    if (lane == 0) wmax[warp] = lmax;
    __syncthreads();
    if (t == 0) {
        float m = wmax[0];
        for (int w = 1; w < 8; w++) m = fmaxf(m, wmax[w]);
        sDmax = m;
    }
    __syncthreads();
    float Dmax = sDmax;

    unsigned long long key[8];
    #pragma unroll
    for (int r = 0; r < 8; r++) {
        float adj = dv[r] + (1.0f - m2v[r]) * Dmax;
        key[r] = ((unsigned long long)__float_as_uint(adj) << 32)
               | (unsigned)(t + r*256);
    }
    {
        unsigned long long best = key[0];
        #pragma unroll
        for (int r = 1; r < 8; r++) if (key[r] < best) best = key[r];
        #pragma unroll
        for (int o = 16; o > 0; o >>= 1) {
            unsigned long long oth = __shfl_xor_sync(0xffffffffu, best, o);
            if (oth < best) best = oth;
        }
        if (lane == 0) buf[0][warp] = best;
    }
    __syncthreads();

    #pragma unroll 1
    for (int it = 0; it < KNB; it++) {
        const unsigned long long* rd = buf[it & 1];
        unsigned long long*       wr = buf[(it + 1) & 1];

        unsigned long long mymin = rd[warp];
        unsigned long long g = rd[0];
        #pragma unroll
        for (int w = 1; w < 8; w++) { unsigned long long v = rd[w]; if (v < g) g = v; }

        if (t == 0) {
            int jm = (int)(unsigned)g;
            g_Eidx[row*KNB + it] = jm;
            g_Dsel[row*KNB + it] = __uint_as_float((unsigned)(g >> 32));
            if (outIdxF) outIdxF[row*KNB + it] = (float)jm;
        }
        if (mymin == g) {
            #pragma unroll
            for (int r = 0; r < 8; r++) if (key[r] == g) key[r] = ~0ull;
            unsigned long long best = key[0];
            #pragma unroll
            for (int r = 1; r < 8; r++) if (key[r] < best) best = key[r];
            #pragma unroll
            for (int o = 16; o > 0; o >>= 1) {
                unsigned long long oth = __shfl_xor_sync(0xffffffffu, best, o);
                if (oth < best) best = oth;
            }
            if (lane == 0) wr[warp] = best;
        } else {
            if (lane == 0) wr[warp] = mymin;
        }
        __syncthreads();
    }
}

// ============================================================
// Kernel 3: edge features (16 RBF banks) -> bf16 hi/lo in global
// exp via FMA-pipe polynomial (no MUFU).
// ============================================================
__global__ __launch_bounds__(128) void feat_kernel(
    const float* __restrict__ X,
    const int*   __restrict__ ridx,
    const int*   __restrict__ chain)
{
    int row = blockIdx.x;
    int b   = row / LSZ;
    int t   = threadIdx.x;

    __shared__ float ia[4][3];
    __shared__ float ja[KNB][4][3];
    __shared__ int   jidx[KNB];
    __shared__ float dsel[KNB];
    __shared__ float dist[KNB][16];     // [0]=dsel, [1..15]=pair dists

    if (t < KNB) { jidx[t] = g_Eidx[row*KNB + t]; dsel[t] = g_Dsel[row*KNB + t]; }
    if (t >= 32 && t < 41) { int r = t - 32; ia[r/3][r%3] = X[row*12 + r]; }
    if (t >= 64 && t < 67) { ia[3][t-64] = g_Cb[row*3 + (t-64)]; }
    __syncthreads();

    for (int s = t; s < KNB*12; s += 128) {
        int k = s / 12, r = s % 12;
        int j = jidx[k];
        if (r < 9) ja[k][r/3][r%3] = X[(b*LSZ + j)*12 + r];
        else       ja[k][3][r-9]   = g_Cb[(b*LSZ + j)*3 + (r-9)];
    }
    if (t < KNB) {
        int j = jidx[t];
        int off  = ridx[row] - ridx[b*LSZ + j];
        int same = (chain[row] == chain[b*LSZ + j]);
        g_Dcode[row*KNB + t] = same ? min(max(off + MAXREL, 0), 2*MAXREL)
                                    : (2*MAXREL + 1);
        dist[t][0] = dsel[t];
    }
    __syncthreads();

    for (int s = t; s < KNB*16; s += 128) {
        int k = s >> 4, p = s & 15;
        if (p < 15) {
            int a = c_PA[p], bb = c_PB[p];
            float dx = ia[a][0] - ja[k][bb][0];
            float dy = ia[a][1] - ja[k][bb][1];
            float dz = ia[a][2] - ja[k][bb][2];
            dist[k][p+1] = sqrtf(dx*dx + dy*dy + dz*dz + 1e-6f);
        }
    }
    __syncthreads();

    // 256 channels per edge, emitted as 128 bf16x2 pairs (hi + lo)
    size_t base = (size_t)row * KNB * 128;
    for (int s = t; s < KNB*128; s += 128) {
        int k  = s >> 7;          // neighbor
        int pr = s & 127;         // pair index: channels 2pr, 2pr+1
        int c0 = pr*2, c1 = c0 + 1;
        float d0 = dist[k][c0 >> 4];
        float d1 = dist[k][c1 >> 4];
        float mu0 = 2.0f + (float)(c0 & 15) * (20.0f/15.0f);
        float mu1 = 2.0f + (float)(c1 & 15) * (20.0f/15.0f);
        float z0 = (d0 - mu0) * 0.8f;
        float z1 = (d1 - mu1) * 0.8f;
        float v0 = exp_neg(z0*z0);
        float v1 = exp_neg(z1*z1);
        __nv_bfloat16 h0 = __float2bfloat16(v0), h1 = __float2bfloat16(v1);
        float l0 = v0 - __bfloat162float(h0);
        float l1 = v1 - __bfloat162float(h1);
        g_Fh[base + s] = pack_bf16x2(h0, h1);
        g_Fl[base + s] = pack_bf16x2(__float2bfloat16(l0), __float2bfloat16(l1));
    }
}

// ============================================================
// Kernel 4: HMMA GEMM [128 edges x 256] @ [256 x 128] + Tpos +
// per-edge layernorm. 512 threads = 16 warps; warp (mh,nq) owns a
// 32x32 C tile. bf16 hi/lo split, 3 mma terms, fp32 accum.
// ============================================================
__global__ __launch_bounds__(512, 1) void gemm_kernel(
    const float* __restrict__ gamma,
    const float* __restrict__ beta,
    float*       __restrict__ outE)
{
    __shared__ __align__(16) __nv_bfloat16 Ah[128][ASTRIDE];
    __shared__ __align__(16) __nv_bfloat16 Al[128][ASTRIDE];
    __shared__ float rowsum[128], rowsq[128], smu[128], sinv[128];

    int t = threadIdx.x, lane = t & 31, w = t >> 5;
    int mh = w >> 2, nq = w & 3;         // warp tile: rows mh*32+, cols nq*32+
    int m0 = blockIdx.x * 128;
    int g  = lane >> 2, tg = lane & 3;

    if (t < 128) { rowsum[t] = 0.f; rowsq[t] = 0.f; }

    float C[2][4][4];
    #pragma unroll
    for (int mf = 0; mf < 2; mf++)
        #pragma unroll
        for (int nf = 0; nf < 4; nf++)
            #pragma unroll
            for (int i = 0; i < 4; i++) C[mf][nf][i] = 0.f;

    for (int kc = 0; kc < 4; kc++) {
        __syncthreads();
        // stage A chunk: 128 rows x 64 bf16 (hi + lo)
        #pragma unroll
        for (int u = 0; u < 4; u++) {
            int idx = t + 512*u;               // 0..2047
            int e = idx >> 4, un = idx & 15;
            size_t goff = (size_t)(m0 + e)*128 + kc*32 + un*2;
            uint2 vh = *reinterpret_cast<const uint2*>(&g_Fh[goff]);
            uint2 vl = *reinterpret_cast<const uint2*>(&g_Fl[goff]);
            *reinterpret_cast<uint2*>(&Ah[e][un*4]) = vh;
            *reinterpret_cast<uint2*>(&Al[e][un*4]) = vl;
        }
        __syncthreads();

        #pragma unroll
        for (int ks = 0; ks < 4; ks++) {
            uint2 bh[4], bl[4];
            int ksg = kc*4 + ks;
            #pragma unroll
            for (int nf = 0; nf < 4; nf++) {
                int gidx = (ksg*16 + nq*4 + nf)*32 + lane;
                bh[nf] = g_WfH[gidx];
                bl[nf] = g_WfL[gidx];
            }
            #pragma unroll
            for (int mf = 0; mf < 2; mf++) {
                int rr = mh*32 + mf*16 + (lane & 15);
                int cc = ks*16 + 8*(lane >> 4);
                uint32_t ah[4], al[4];
                ldsm_x4(ah, smem_to_u32(&Ah[rr][cc]));
                ldsm_x4(al, smem_to_u32(&Al[rr][cc]));
                #pragma unroll
                for (int nf = 0; nf < 4; nf++) {
                    mma_bf16(C[mf][nf], ah, reinterpret_cast<uint32_t*>(&bh[nf]));
                    mma_bf16(C[mf][nf], ah, reinterpret_cast<uint32_t*>(&bl[nf]));
                    mma_bf16(C[mf][nf], al, reinterpret_cast<uint32_t*>(&bh[nf]));
                }
            }
        }
    }

    // ---- epilogue: +Tpos, row sums (quad shfl + smem atomics) ----
    #pragma unroll
    for (int mf = 0; mf < 2; mf++) {
        int r0 = mh*32 + mf*16 + g;          // local rows r0, r0+8
        int dc0 = g_Dcode[m0 + r0];
        int dc1 = g_Dcode[m0 + r0 + 8];
        float s0 = 0.f, q0 = 0.f, s1 = 0.f, q1 = 0.f;
        #pragma unroll
        for (int nf = 0; nf < 4; nf++) {
            int col = nq*32 + nf*8 + tg*2;
            float2 t0 = *reinterpret_cast<const float2*>(&g_Tpos[dc0*NOUT + col]);
            float2 t1 = *reinterpret_cast<const float2*>(&g_Tpos[dc1*NOUT + col]);
            C[mf][nf][0] += t0.x;  C[mf][nf][1] += t0.y;
            C[mf][nf][2] += t1.x;  C[mf][nf][3] += t1.y;
            s0 += C[mf][nf][0] + C[mf][nf][1];
            q0 += C[mf][nf][0]*C[mf][nf][0] + C[mf][nf][1]*C[mf][nf][1];
            s1 += C[mf][nf][2] + C[mf][nf][3];
            q1 += C[mf][nf][2]*C[mf][nf][2] + C[mf][nf][3]*C[mf][nf][3];
        }
        s0 += __shfl_xor_sync(0xffffffffu, s0, 1);
        s0 += __shfl_xor_sync(0xffffffffu, s0, 2);
        q0 += __shfl_xor_sync(0xffffffffu, q0, 1);
        q0 += __shfl_xor_sync(0xffffffffu, q0, 2);
        s1 += __shfl_xor_sync(0xffffffffu, s1, 1);
        s1 += __shfl_xor_sync(0xffffffffu, s1, 2);
        q1 += __shfl_xor_sync(0xffffffffu, q1, 1);
        q1 += __shfl_xor_sync(0xffffffffu, q1, 2);
        if (tg == 0) {
            atomicAdd(&rowsum[r0],     s0);
            atomicAdd(&rowsq [r0],     q0);
            atomicAdd(&rowsum[r0 + 8], s1);
            atomicAdd(&rowsq [r0 + 8], q1);
        }
    }
    __syncthreads();
    if (t < 128) {
        float mu  = rowsum[t] * (1.0f/NOUT);
        float var = fmaxf(rowsq[t] * (1.0f/NOUT) - mu*mu, 0.0f);
        smu[t]  = mu;
        sinv[t] = rsqrtf(var + 1e-5f);
    }
    __syncthreads();

    #pragma unroll
    for (int mf = 0; mf < 2; mf++) {
        int r0 = mh*32 + mf*16 + g;
        float mu0 = smu[r0],   iv0 = sinv[r0];
        float mu1 = smu[r0+8], iv1 = sinv[r0+8];
        #pragma unroll
        for (int nf = 0; nf < 4; nf++) {
            int col = nq*32 + nf*8 + tg*2;
            float2 gm = *reinterpret_cast<const float2*>(&gamma[col]);
            float2 bt = *reinterpret_cast<const float2*>(&beta [col]);
            float2 o0, o1;
            o0.x = (C[mf][nf][0] - mu0)*iv0*gm.x + bt.x;
            o0.y = (C[mf][nf][1] - mu0)*iv0*gm.y + bt.y;
            o1.x = (C[mf][nf][2] - mu1)*iv1*gm.x + bt.x;
            o1.y = (C[mf][nf][3] - mu1)*iv1*gm.y + bt.y;
            *reinterpret_cast<float2*>(&outE[(size_t)(m0 + r0    )*NOUT + col]) = o0;
            *reinterpret_cast<float2*>(&outE[(size_t)(m0 + r0 + 8)*NOUT + col]) = o1;
        }
    }
}

// ============================================================
extern "C" void kernel_launch(void* const* d_in, const int* in_sizes, int n_in,
                              void* d_out, int out_size)
{
    const float* X      = (const float*)d_in[0];
    const float* mask   = (const float*)d_in[1];
    const int*   ridx   = (const int*)  d_in[2];
    const int*   chain  = (const int*)  d_in[3];
    const float* W_pos  = (const float*)d_in[4];
    const float* b_pos  = (const float*)d_in[5];
    const float* W_edge = (const float*)d_in[6];
    const float* gamma  = (const float*)d_in[7];
    const float* beta   = (const float*)d_in[8];

    float* outE = (float*)d_out;
    long long esz = (long long)NEDGE*NOUT;           // 31,457,280
    float* outIdxF = ((long long)out_size > esz) ? (outE + esz) : nullptr;

    tpos_kernel<<<NDC, NOUT>>>(W_pos, b_pos, W_edge);
    wprep_kernel<<<32, 256>>>(W_edge);
    cb_kernel  <<<(BSZ*LSZ + 255)/256, 256>>>(X);
    topk_kernel<<<BSZ*LSZ, 256>>>(X, mask, outIdxF);
    feat_kernel<<<BSZ*LSZ, 128>>>(X, ridx, chain);
    gemm_kernel<<<MTILES, 512>>>(gamma, beta, outE);
}

// round 13
// speedup vs baseline: 2.1800x; 1.0742x over previous
#include <cuda_runtime.h>
#include <cuda_bf16.h>
#include <cstdint>

// Problem constants (shapes fixed by setup_inputs)
#define BSZ   4
#define LSZ   2048
#define KNB   30      // TOP_K
#define NRB   256     // 16 banks * 16 rbf channels (positional via table)
#define NOUT  128
#define MAXREL 32
#define NDC   66      // dcode values: 0..64 same-chain, 65 cross-chain
#define NEDGE (BSZ*LSZ*KNB)     // 245760
#define MTILES (NEDGE/128)      // 1920 (exact)
#define ASTRIDE 72              // smem A row stride in bf16 (144B, 16B-aligned)
#define NBUCK 2048              // topk histogram buckets (float bits >> 20)
#define CAP   512               // candidate buffer bound

// -------- device scratch (no cudaMalloc allowed) --------
__device__ float    g_Cb  [BSZ*LSZ*3];
__device__ float4   g_C4  [BSZ*LSZ];           // (Cx,Cy,Cz,mask) packed
__device__ int      g_Eidx[NEDGE];
__device__ float    g_Dsel[NEDGE];
__device__ int      g_Dcode[NEDGE];
__device__ float    g_Tpos[NDC*NOUT];          // (W_pos[d]+b_pos) @ W_edge[0:16]
__device__ uint32_t g_Fh[(size_t)NEDGE*128];   // features hi, bf16x2 pairs
__device__ uint32_t g_Fl[(size_t)NEDGE*128];   // features lo
__device__ uint2    g_WfH[16*16*32];           // W hi, B-fragment layout [ks][nf][lane]
__device__ uint2    g_WfL[16*16*32];           // W lo

// pair tables: dist(A_atom of residue i, B_atom of residue j)
// atom codes: 0=N, 1=C, 2=Ca, 3=Cb(virtual)
__constant__ int c_PA[15] = {0,2,3,1,1,1,0,0,3,0,2,3,2,3,2};
__constant__ int c_PB[15] = {0,2,3,0,2,3,2,3,2,1,1,1,0,0,3};

// ---------- helpers ----------
__device__ __forceinline__ uint32_t pack_bf16x2(__nv_bfloat16 lo, __nv_bfloat16 hi) {
    uint32_t l = (uint32_t)__bfloat16_as_ushort(lo);
    uint32_t h = (uint32_t)__bfloat16_as_ushort(hi);
    return l | (h << 16);
}
__device__ __forceinline__ uint32_t smem_to_u32(const void* p) {
    uint32_t a;
    asm("{ .reg .u64 t; cvta.to.shared.u64 t, %1; cvt.u32.u64 %0, t; }"
        : "=r"(a) : "l"(p));
    return a;
}
__device__ __forceinline__ void ldsm_x4(uint32_t* r, uint32_t addr) {
    asm volatile("ldmatrix.sync.aligned.m8n8.x4.shared.b16 {%0,%1,%2,%3}, [%4];"
        : "=r"(r[0]), "=r"(r[1]), "=r"(r[2]), "=r"(r[3]) : "r"(addr));
}
__device__ __forceinline__ void mma_bf16(float* c, const uint32_t* a,
                                         const uint32_t* b) {
    asm volatile(
        "mma.sync.aligned.m16n8k16.row.col.f32.bf16.bf16.f32 "
        "{%0,%1,%2,%3}, {%4,%5,%6,%7}, {%8,%9}, {%0,%1,%2,%3};"
        : "+f"(c[0]), "+f"(c[1]), "+f"(c[2]), "+f"(c[3])
        : "r"(a[0]), "r"(a[1]), "r"(a[2]), "r"(a[3]), "r"(b[0]), "r"(b[1]));
}
// exp(-u), u >= 0, FMA/ALU pipes only (no MUFU). ~1e-7 rel.
__device__ __forceinline__ float exp_neg(float u) {
    float t = fmaxf(-u * 1.4426950408889634f, -150.0f);
    float k = rintf(t);
    float f = t - k;
    float p =        1.5403530393e-4f;
    p = fmaf(p, f, 1.3333558146e-3f);
    p = fmaf(p, f, 9.6181291076e-3f);
    p = fmaf(p, f, 5.5504108665e-2f);
    p = fmaf(p, f, 2.4022650696e-1f);
    p = fmaf(p, f, 6.9314718056e-1f);
    p = fmaf(p, f, 1.0f);
    int ki = (int)k;
    int k1 = ki >> 1, k2 = ki - k1;        // two-step scale, no underflow wrap
    float s1 = __int_as_float((k1 + 127) << 23);
    float s2 = __int_as_float((k2 + 127) << 23);
    return p * s1 * s2;
}

// ============================================================
// Kernel 0a: positional projection table
// ============================================================
__global__ void tpos_kernel(const float* __restrict__ W_pos,
                            const float* __restrict__ b_pos,
                            const float* __restrict__ W_edge)
{
    int d = blockIdx.x, t = threadIdx.x;
    float acc = 0.f;
    #pragma unroll
    for (int f = 0; f < 16; f++)
        acc = fmaf(W_pos[d*16 + f] + b_pos[f], W_edge[f*NOUT + t], acc);
    g_Tpos[d*NOUT + t] = acc;
}

// Kernel 0b: W -> bf16 hi/lo in exact mma.sync B-fragment order.
__global__ void wprep_kernel(const float* __restrict__ W_edge)
{
    int idx = blockIdx.x*256 + threadIdx.x;      // 8192 frags
    int lane = idx & 31, nfg = (idx >> 5) & 15, ks = idx >> 9;
    int n = nfg*8 + (lane >> 2);
    int k = ks*16 + 2*(lane & 3);
    float w[4];
    w[0] = W_edge[(16 + k    )*NOUT + n];
    w[1] = W_edge[(16 + k + 1)*NOUT + n];
    w[2] = W_edge[(16 + k + 8)*NOUT + n];
    w[3] = W_edge[(16 + k + 9)*NOUT + n];
    __nv_bfloat16 h[4]; float l[4];
    #pragma unroll
    for (int i = 0; i < 4; i++) {
        h[i] = __float2bfloat16(w[i]);
        l[i] = w[i] - __bfloat162float(h[i]);
    }
    uint2 uh, ul;
    uh.x = pack_bf16x2(h[0], h[1]);
    uh.y = pack_bf16x2(h[2], h[3]);
    ul.x = pack_bf16x2(__float2bfloat16(l[0]), __float2bfloat16(l[1]));
    ul.y = pack_bf16x2(__float2bfloat16(l[2]), __float2bfloat16(l[3]));
    g_WfH[idx] = uh;
    g_WfL[idx] = ul;
}

// ============================================================
// Kernel 1: virtual C-beta + packed (C,mask) float4
// ============================================================
__global__ void cb_kernel(const float* __restrict__ X,
                          const float* __restrict__ mask)
{
    int i = blockIdx.x * 256 + threadIdx.x;
    if (i >= BSZ*LSZ) return;
    const float* x = &X[i*12];
    float Nx=x[0],  Ny=x[1],  Nz=x[2];
    float Cx=x[3],  Cy=x[4],  Cz=x[5];
    float Ax=x[6],  Ay=x[7],  Az=x[8];
    float bx=Ax-Nx, by=Ay-Ny, bz=Az-Nz;
    float cx=Cx-Ax, cy=Cy-Ay, cz=Cz-Az;
    float ax = by*cz - bz*cy;
    float ay = bz*cx - bx*cz;
    float az = bx*cy - by*cx;
    g_Cb[i*3+0] = -0.58273431f*ax + 0.56802827f*bx - 0.54067466f*cx + Ax;
    g_Cb[i*3+1] = -0.58273431f*ay + 0.56802827f*by - 0.54067466f*cy + Ay;
    g_Cb[i*3+2] = -0.58273431f*az + 0.56802827f*bz - 0.54067466f*cz + Az;
    g_C4[i] = make_float4(Cx, Cy, Cz, mask[i]);
}

// ============================================================
// Kernel 2: masked pairwise C-C distances + EXACT top-30 via
// histogram select. key = (adj_bits << 32) | j; bucket = bits>>20
// is monotone in adj, so all top-30 keys live in buckets <= B where
// B is the bucket at which cum count reaches 30. Candidates
// (~40-60) are compacted and one warp runs the exact 30-round
// extraction (stable tie-break preserved).
// ============================================================
__global__ __launch_bounds__(256) void topk_kernel(float* __restrict__ outIdxF)
{
    int row = blockIdx.x;
    int b   = row / LSZ;
    int t   = threadIdx.x;
    int warp = t >> 5, lane = t & 31;

    __shared__ float wmax[8];
    __shared__ float sDmax;
    __shared__ uint32_t hist[NBUCK];
    __shared__ int sB;
    __shared__ int scnt;
    __shared__ unsigned long long cand[CAP];

    float4 me = g_C4[row];
    float mi = me.w;

    float dv[8], m2v[8];
    float lmax = 0.f;
    #pragma unroll
    for (int r = 0; r < 8; r++) {
        int j = t + r*256;
        float4 pj = g_C4[b*LSZ + j];
        float dx = me.x-pj.x, dy = me.y-pj.y, dz = me.z-pj.z;
        float d  = sqrtf(dx*dx + dy*dy + dz*dz + 1e-6f);
        float m2 = mi * pj.w;
        dv[r]  = m2 * d;
        m2v[r] = m2;
        lmax = fmaxf(lmax, dv[r]);
    }
    #pragma unroll
    for (int o = 16; o > 0; o >>= 1)
        lmax = fmaxf(lmax, __shfl_xor_sync(0xffffffffu, lmax, o));
    if (lane == 0) wmax[warp] = lmax;
    // zero histogram + counter while the max reduction settles
    #pragma unroll
    for (int h = 0; h < NBUCK/256; h++) hist[t + h*256] = 0;
    if (t == 0) scnt = 0;
    __syncthreads();
    if (t == 0) {
        float m = wmax[0];
        for (int w = 1; w < 8; w++) m = fmaxf(m, wmax[w]);
        sDmax = m;
    }
    __syncthreads();
    float Dmax = sDmax;

    unsigned long long key[8];
    #pragma unroll
    for (int r = 0; r < 8; r++) {
        float adj = dv[r] + (1.0f - m2v[r]) * Dmax;      // D_adjust
        key[r] = ((unsigned long long)__float_as_uint(adj) << 32)
               | (unsigned)(t + r*256);
        atomicAdd(&hist[(unsigned)(key[r] >> 52)], 1u);
    }
    __syncthreads();

    // warp 0: find threshold bucket B (cum count reaches KNB)
    if (warp == 0) {
        int base = lane * (NBUCK/32);
        int s = 0;
        #pragma unroll 8
        for (int c = 0; c < NBUCK/32; c++) s += (int)hist[base + c];
        int pre = s;
        #pragma unroll
        for (int o = 1; o < 32; o <<= 1) {
            int v = __shfl_up_sync(0xffffffffu, pre, o);
            if (lane >= o) pre += v;
        }
        pre -= s;                         // exclusive prefix
        if (pre < KNB && pre + s >= KNB) {
            int acc = pre, Bq = base + NBUCK/32 - 1;
            for (int c = 0; c < NBUCK/32; c++) {
                acc += (int)hist[base + c];
                if (acc >= KNB) { Bq = base + c; break; }
            }
            sB = Bq;
        }
    }
    __syncthreads();

    // compact candidates (all keys in buckets <= B; superset of top-30)
    int B = sB;
    #pragma unroll
    for (int r = 0; r < 8; r++) {
        if ((int)(unsigned)(key[r] >> 52) <= B) {
            int p = atomicAdd(&scnt, 1);
            if (p < CAP) cand[p] = key[r];
        }
    }
    __syncthreads();

    // warp 0: exact 30-round extraction over the candidates
    if (warp == 0) {
        int cnt = min(scnt, CAP);
        unsigned long long k2[CAP/32];
        #pragma unroll
        for (int r = 0; r < CAP/32; r++) {
            int idx = lane + r*32;
            k2[r] = (idx < cnt) ? cand[idx] : ~0ull;
        }
        unsigned long long locmin = k2[0];
        #pragma unroll
        for (int r = 1; r < CAP/32; r++)
            if (k2[r] < locmin) locmin = k2[r];

        #pragma unroll 1
        for (int it = 0; it < KNB; it++) {
            unsigned long long g = locmin;
            #pragma unroll
            for (int o = 16; o > 0; o >>= 1) {
                unsigned long long oth = __shfl_xor_sync(0xffffffffu, g, o);
                if (oth < g) g = oth;
            }
            if (lane == 0) {
                int jm = (int)(unsigned)g;
                g_Eidx[row*KNB + it] = jm;
                g_Dsel[row*KNB + it] = __uint_as_float((unsigned)(g >> 32));
                if (outIdxF) outIdxF[row*KNB + it] = (float)jm;
            }
            if (locmin == g) {            // exactly one lane (keys unique)
                #pragma unroll
                for (int r = 0; r < CAP/32; r++) if (k2[r] == g) k2[r] = ~0ull;
                locmin = k2[0];
                #pragma unroll
                for (int r = 1; r < CAP/32; r++)
                    if (k2[r] < locmin) locmin = k2[r];
            }
        }
    }
}

// ============================================================
// Kernel 3: edge features (16 RBF banks) -> bf16 hi/lo in global
// exp via FMA-pipe polynomial (no MUFU).
// ============================================================
__global__ __launch_bounds__(128) void feat_kernel(
    const float* __restrict__ X,
    const int*   __restrict__ ridx,
    const int*   __restrict__ chain)
{
    int row = blockIdx.x;
    int b   = row / LSZ;
    int t   = threadIdx.x;

    __shared__ float ia[4][3];
    __shared__ float ja[KNB][4][3];
    __shared__ int   jidx[KNB];
    __shared__ float dsel[KNB];
    __shared__ float dist[KNB][16];     // [0]=dsel, [1..15]=pair dists

    if (t < KNB) { jidx[t] = g_Eidx[row*KNB + t]; dsel[t] = g_Dsel[row*KNB + t]; }
    if (t >= 32 && t < 41) { int r = t - 32; ia[r/3][r%3] = X[row*12 + r]; }
    if (t >= 64 && t < 67) { ia[3][t-64] = g_Cb[row*3 + (t-64)]; }
    __syncthreads();

    for (int s = t; s < KNB*12; s += 128) {
        int k = s / 12, r = s % 12;
        int j = jidx[k];
        if (r < 9) ja[k][r/3][r%3] = X[(b*LSZ + j)*12 + r];
        else       ja[k][3][r-9]   = g_Cb[(b*LSZ + j)*3 + (r-9)];
    }
    if (t < KNB) {
        int j = jidx[t];
        int off  = ridx[row] - ridx[b*LSZ + j];
        int same = (chain[row] == chain[b*LSZ + j]);
        g_Dcode[row*KNB + t] = same ? min(max(off + MAXREL, 0), 2*MAXREL)
                                    : (2*MAXREL + 1);
        dist[t][0] = dsel[t];
    }
    __syncthreads();

    for (int s = t; s < KNB*16; s += 128) {
        int k = s >> 4, p = s & 15;
        if (p < 15) {
            int a = c_PA[p], bb = c_PB[p];
            float dx = ia[a][0] - ja[k][bb][0];
            float dy = ia[a][1] - ja[k][bb][1];
            float dz = ia[a][2] - ja[k][bb][2];
            dist[k][p+1] = sqrtf(dx*dx + dy*dy + dz*dz + 1e-6f);
        }
    }
    __syncthreads();

    // 256 channels per edge, emitted as 128 bf16x2 pairs (hi + lo)
    size_t base = (size_t)row * KNB * 128;
    for (int s = t; s < KNB*128; s += 128) {
        int k  = s >> 7;          // neighbor
        int pr = s & 127;         // pair index: channels 2pr, 2pr+1
        int c0 = pr*2, c1 = c0 + 1;
        float d0 = dist[k][c0 >> 4];
        float d1 = dist[k][c1 >> 4];
        float mu0 = 2.0f + (float)(c0 & 15) * (20.0f/15.0f);
        float mu1 = 2.0f + (float)(c1 & 15) * (20.0f/15.0f);
        float z0 = (d0 - mu0) * 0.8f;
        float z1 = (d1 - mu1) * 0.8f;
        float v0 = exp_neg(z0*z0);
        float v1 = exp_neg(z1*z1);
        __nv_bfloat16 h0 = __float2bfloat16(v0), h1 = __float2bfloat16(v1);
        float l0 = v0 - __bfloat162float(h0);
        float l1 = v1 - __bfloat162float(h1);
        g_Fh[base + s] = pack_bf16x2(h0, h1);
        g_Fl[base + s] = pack_bf16x2(__float2bfloat16(l0), __float2bfloat16(l1));
    }
}

// ============================================================
// Kernel 4: HMMA GEMM [128 edges x 256] @ [256 x 128] + Tpos +
// per-edge layernorm. 512 threads = 16 warps; warp (mh,nq) owns a
// 32x32 C tile. bf16 hi/lo split, 3 mma terms, fp32 accum.
// ============================================================
__global__ __launch_bounds__(512, 1) void gemm_kernel(
    const float* __restrict__ gamma,
    const float* __restrict__ beta,
    float*       __restrict__ outE)
{
    __shared__ __align__(16) __nv_bfloat16 Ah[128][ASTRIDE];
    __shared__ __align__(16) __nv_bfloat16 Al[128][ASTRIDE];
    __shared__ float rowsum[128], rowsq[128], smu[128], sinv[128];

    int t = threadIdx.x, lane = t & 31, w = t >> 5;
    int mh = w >> 2, nq = w & 3;         // warp tile: rows mh*32+, cols nq*32+
    int m0 = blockIdx.x * 128;
    int g  = lane >> 2, tg = lane & 3;

    if (t < 128) { rowsum[t] = 0.f; rowsq[t] = 0.f; }

    float C[2][4][4];
    #pragma unroll
    for (int mf = 0; mf < 2; mf++)
        #pragma unroll
        for (int nf = 0; nf < 4; nf++)
            #pragma unroll
            for (int i = 0; i < 4; i++) C[mf][nf][i] = 0.f;

    for (int kc = 0; kc < 4; kc++) {
        __syncthreads();
        // stage A chunk: 128 rows x 64 bf16 (hi + lo)
        #pragma unroll
        for (int u = 0; u < 4; u++) {
            int idx = t + 512*u;               // 0..2047
            int e = idx >> 4, un = idx & 15;
            size_t goff = (size_t)(m0 + e)*128 + kc*32 + un*2;
            uint2 vh = *reinterpret_cast<const uint2*>(&g_Fh[goff]);
            uint2 vl = *reinterpret_cast<const uint2*>(&g_Fl[goff]);
            *reinterpret_cast<uint2*>(&Ah[e][un*4]) = vh;
            *reinterpret_cast<uint2*>(&Al[e][un*4]) = vl;
        }
        __syncthreads();

        #pragma unroll
        for (int ks = 0; ks < 4; ks++) {
            uint2 bh[4], bl[4];
            int ksg = kc*4 + ks;
            #pragma unroll
            for (int nf = 0; nf < 4; nf++) {
                int gidx = (ksg*16 + nq*4 + nf)*32 + lane;
                bh[nf] = g_WfH[gidx];
                bl[nf] = g_WfL[gidx];
            }
            #pragma unroll
            for (int mf = 0; mf < 2; mf++) {
                int rr = mh*32 + mf*16 + (lane & 15);
                int cc = ks*16 + 8*(lane >> 4);
                uint32_t ah[4], al[4];
                ldsm_x4(ah, smem_to_u32(&Ah[rr][cc]));
                ldsm_x4(al, smem_to_u32(&Al[rr][cc]));
                #pragma unroll
                for (int nf = 0; nf < 4; nf++) {
                    mma_bf16(C[mf][nf], ah, reinterpret_cast<uint32_t*>(&bh[nf]));
                    mma_bf16(C[mf][nf], ah, reinterpret_cast<uint32_t*>(&bl[nf]));
                    mma_bf16(C[mf][nf], al, reinterpret_cast<uint32_t*>(&bh[nf]));
                }
            }
        }
    }

    // ---- epilogue: +Tpos, row sums (quad shfl + smem atomics) ----
    #pragma unroll
    for (int mf = 0; mf < 2; mf++) {
        int r0 = mh*32 + mf*16 + g;          // local rows r0, r0+8
        int dc0 = g_Dcode[m0 + r0];
        int dc1 = g_Dcode[m0 + r0 + 8];
        float s0 = 0.f, q0 = 0.f, s1 = 0.f, q1 = 0.f;
        #pragma unroll
        for (int nf = 0; nf < 4; nf++) {
            int col = nq*32 + nf*8 + tg*2;
            float2 t0 = *reinterpret_cast<const float2*>(&g_Tpos[dc0*NOUT + col]);
            float2 t1 = *reinterpret_cast<const float2*>(&g_Tpos[dc1*NOUT + col]);
            C[mf][nf][0] += t0.x;  C[mf][nf][1] += t0.y;
            C[mf][nf][2] += t1.x;  C[mf][nf][3] += t1.y;
            s0 += C[mf][nf][0] + C[mf][nf][1];
            q0 += C[mf][nf][0]*C[mf][nf][0] + C[mf][nf][1]*C[mf][nf][1];
            s1 += C[mf][nf][2] + C[mf][nf][3];
            q1 += C[mf][nf][2]*C[mf][nf][2] + C[mf][nf][3]*C[mf][nf][3];
        }
        s0 += __shfl_xor_sync(0xffffffffu, s0, 1);
        s0 += __shfl_xor_sync(0xffffffffu, s0, 2);
        q0 += __shfl_xor_sync(0xffffffffu, q0, 1);
        q0 += __shfl_xor_sync(0xffffffffu, q0, 2);
        s1 += __shfl_xor_sync(0xffffffffu, s1, 1);
        s1 += __shfl_xor_sync(0xffffffffu, s1, 2);
        q1 += __shfl_xor_sync(0xffffffffu, q1, 1);
        q1 += __shfl_xor_sync(0xffffffffu, q1, 2);
        if (tg == 0) {
            atomicAdd(&rowsum[r0],     s0);
            atomicAdd(&rowsq [r0],     q0);
            atomicAdd(&rowsum[r0 + 8], s1);
            atomicAdd(&rowsq [r0 + 8], q1);
        }
    }
    __syncthreads();
    if (t < 128) {
        float mu  = rowsum[t] * (1.0f/NOUT);
        float var = fmaxf(rowsq[t] * (1.0f/NOUT) - mu*mu, 0.0f);
        smu[t]  = mu;
        sinv[t] = rsqrtf(var + 1e-5f);
    }
    __syncthreads();

    #pragma unroll
    for (int mf = 0; mf < 2; mf++) {
        int r0 = mh*32 + mf*16 + g;
        float mu0 = smu[r0],   iv0 = sinv[r0];
        float mu1 = smu[r0+8], iv1 = sinv[r0+8];
        #pragma unroll
        for (int nf = 0; nf < 4; nf++) {
            int col = nq*32 + nf*8 + tg*2;
            float2 gm = *reinterpret_cast<const float2*>(&gamma[col]);
            float2 bt = *reinterpret_cast<const float2*>(&beta [col]);
            float2 o0, o1;
            o0.x = (C[mf][nf][0] - mu0)*iv0*gm.x + bt.x;
            o0.y = (C[mf][nf][1] - mu0)*iv0*gm.y + bt.y;
            o1.x = (C[mf][nf][2] - mu1)*iv1*gm.x + bt.x;
            o1.y = (C[mf][nf][3] - mu1)*iv1*gm.y + bt.y;
            *reinterpret_cast<float2*>(&outE[(size_t)(m0 + r0    )*NOUT + col]) = o0;
            *reinterpret_cast<float2*>(&outE[(size_t)(m0 + r0 + 8)*NOUT + col]) = o1;
        }
    }
}

// ============================================================
extern "C" void kernel_launch(void* const* d_in, const int* in_sizes, int n_in,
                              void* d_out, int out_size)
{
    const float* X      = (const float*)d_in[0];
    const float* mask   = (const float*)d_in[1];
    const int*   ridx   = (const int*)  d_in[2];
    const int*   chain  = (const int*)  d_in[3];
    const float* W_pos  = (const float*)d_in[4];
    const float* b_pos  = (const float*)d_in[5];
    const float* W_edge = (const float*)d_in[6];
    const float* gamma  = (const float*)d_in[7];
    const float* beta   = (const float*)d_in[8];

    float* outE = (float*)d_out;
    long long esz = (long long)NEDGE*NOUT;           // 31,457,280
    float* outIdxF = ((long long)out_size > esz) ? (outE + esz) : nullptr;

    tpos_kernel<<<NDC, NOUT>>>(W_pos, b_pos, W_edge);
    wprep_kernel<<<32, 256>>>(W_edge);
    cb_kernel  <<<(BSZ*LSZ + 255)/256, 256>>>(X, mask);
    topk_kernel<<<BSZ*LSZ, 256>>>(outIdxF);
    feat_kernel<<<BSZ*LSZ, 128>>>(X, ridx, chain);
    gemm_kernel<<<MTILES, 512>>>(gamma, beta, outE);
}

// round 14
// speedup vs baseline: 2.5317x; 1.1614x over previous
#include <cuda_runtime.h>
#include <cuda_bf16.h>
#include <cstdint>

// Problem constants (shapes fixed by setup_inputs)
#define BSZ   4
#define LSZ   2048
#define KNB   30      // TOP_K
#define NRB   256     // 16 banks * 16 rbf channels (positional via table)
#define NOUT  128
#define MAXREL 32
#define NDC   66      // dcode values: 0..64 same-chain, 65 cross-chain
#define NEDGE (BSZ*LSZ*KNB)     // 245760
#define MTILES (NEDGE/128)      // 1920 (exact)
#define ASTRIDE 72              // smem A row stride in bf16 (144B, 16B-aligned)
#define NBUCK 2048              // topk histogram buckets (float bits >> 20)
#define CAP   512               // candidate buffer bound

// -------- device scratch (no cudaMalloc allowed) --------
__device__ float    g_Cb  [BSZ*LSZ*3];
__device__ float4   g_C4  [BSZ*LSZ];           // (Cx,Cy,Cz,mask) packed
__device__ int      g_Eidx[NEDGE];
__device__ float    g_Dsel[NEDGE];
__device__ int      g_Dcode[NEDGE];
__device__ float    g_Tpos[NDC*NOUT];          // (W_pos[d]+b_pos) @ W_edge[0:16]
__device__ uint32_t g_Fh[(size_t)NEDGE*128];   // features hi, bf16x2 pairs
__device__ uint32_t g_Fl[(size_t)NEDGE*128];   // features lo
__device__ uint2    g_WfH[16*16*32];           // W hi, B-fragment layout [ks][nf][lane]
__device__ uint2    g_WfL[16*16*32];           // W lo

// pair tables: dist(A_atom of residue i, B_atom of residue j)
// atom codes: 0=N, 1=C, 2=Ca, 3=Cb(virtual)
__constant__ int c_PA[15] = {0,2,3,1,1,1,0,0,3,0,2,3,2,3,2};
__constant__ int c_PB[15] = {0,2,3,0,2,3,2,3,2,1,1,1,0,0,3};

// ---------- helpers ----------
__device__ __forceinline__ uint32_t pack_bf16x2(__nv_bfloat16 lo, __nv_bfloat16 hi) {
    uint32_t l = (uint32_t)__bfloat16_as_ushort(lo);
    uint32_t h = (uint32_t)__bfloat16_as_ushort(hi);
    return l | (h << 16);
}
__device__ __forceinline__ uint32_t smem_to_u32(const void* p) {
    uint32_t a;
    asm("{ .reg .u64 t; cvta.to.shared.u64 t, %1; cvt.u32.u64 %0, t; }"
        : "=r"(a) : "l"(p));
    return a;
}
__device__ __forceinline__ void ldsm_x4(uint32_t* r, uint32_t addr) {
    asm volatile("ldmatrix.sync.aligned.m8n8.x4.shared.b16 {%0,%1,%2,%3}, [%4];"
        : "=r"(r[0]), "=r"(r[1]), "=r"(r[2]), "=r"(r[3]) : "r"(addr));
}
__device__ __forceinline__ void mma_bf16(float* c, const uint32_t* a,
                                         const uint32_t* b) {
    asm volatile(
        "mma.sync.aligned.m16n8k16.row.col.f32.bf16.bf16.f32 "
        "{%0,%1,%2,%3}, {%4,%5,%6,%7}, {%8,%9}, {%0,%1,%2,%3};"
        : "+f"(c[0]), "+f"(c[1]), "+f"(c[2]), "+f"(c[3])
        : "r"(a[0]), "r"(a[1]), "r"(a[2]), "r"(a[3]), "r"(b[0]), "r"(b[1]));
}
// exp(-u), u >= 0, FMA/ALU pipes only (no MUFU). ~1e-7 rel.
__device__ __forceinline__ float exp_neg(float u) {
    float t = fmaxf(-u * 1.4426950408889634f, -150.0f);
    float k = rintf(t);
    float f = t - k;
    float p =        1.5403530393e-4f;
    p = fmaf(p, f, 1.3333558146e-3f);
    p = fmaf(p, f, 9.6181291076e-3f);
    p = fmaf(p, f, 5.5504108665e-2f);
    p = fmaf(p, f, 2.4022650696e-1f);
    p = fmaf(p, f, 6.9314718056e-1f);
    p = fmaf(p, f, 1.0f);
    int ki = (int)k;
    int k1 = ki >> 1, k2 = ki - k1;        // two-step scale, no underflow wrap
    float s1 = __int_as_float((k1 + 127) << 23);
    float s2 = __int_as_float((k2 + 127) << 23);
    return p * s1 * s2;
}

// ============================================================
// Kernel 0a: positional projection table
// ============================================================
__global__ void tpos_kernel(const float* __restrict__ W_pos,
                            const float* __restrict__ b_pos,
                            const float* __restrict__ W_edge)
{
    int d = blockIdx.x, t = threadIdx.x;
    float acc = 0.f;
    #pragma unroll
    for (int f = 0; f < 16; f++)
        acc = fmaf(W_pos[d*16 + f] + b_pos[f], W_edge[f*NOUT + t], acc);
    g_Tpos[d*NOUT + t] = acc;
}

// Kernel 0b: W -> bf16 hi/lo in exact mma.sync B-fragment order.
__global__ void wprep_kernel(const float* __restrict__ W_edge)
{
    int idx = blockIdx.x*256 + threadIdx.x;      // 8192 frags
    int lane = idx & 31, nfg = (idx >> 5) & 15, ks = idx >> 9;
    int n = nfg*8 + (lane >> 2);
    int k = ks*16 + 2*(lane & 3);
    float w[4];
    w[0] = W_edge[(16 + k    )*NOUT + n];
    w[1] = W_edge[(16 + k + 1)*NOUT + n];
    w[2] = W_edge[(16 + k + 8)*NOUT + n];
    w[3] = W_edge[(16 + k + 9)*NOUT + n];
    __nv_bfloat16 h[4]; float l[4];
    #pragma unroll
    for (int i = 0; i < 4; i++) {
        h[i] = __float2bfloat16(w[i]);
        l[i] = w[i] - __bfloat162float(h[i]);
    }
    uint2 uh, ul;
    uh.x = pack_bf16x2(h[0], h[1]);
    uh.y = pack_bf16x2(h[2], h[3]);
    ul.x = pack_bf16x2(__float2bfloat16(l[0]), __float2bfloat16(l[1]));
    ul.y = pack_bf16x2(__float2bfloat16(l[2]), __float2bfloat16(l[3]));
    g_WfH[idx] = uh;
    g_WfL[idx] = ul;
}

// ============================================================
// Kernel 1: virtual C-beta + packed (C,mask) float4
// ============================================================
__global__ void cb_kernel(const float* __restrict__ X,
                          const float* __restrict__ mask)
{
    int i = blockIdx.x * 256 + threadIdx.x;
    if (i >= BSZ*LSZ) return;
    const float* x = &X[i*12];
    float Nx=x[0],  Ny=x[1],  Nz=x[2];
    float Cx=x[3],  Cy=x[4],  Cz=x[5];
    float Ax=x[6],  Ay=x[7],  Az=x[8];
    float bx=Ax-Nx, by=Ay-Ny, bz=Az-Nz;
    float cx=Cx-Ax, cy=Cy-Ay, cz=Cz-Az;
    float ax = by*cz - bz*cy;
    float ay = bz*cx - bx*cz;
    float az = bx*cy - by*cx;
    g_Cb[i*3+0] = -0.58273431f*ax + 0.56802827f*bx - 0.54067466f*cx + Ax;
    g_Cb[i*3+1] = -0.58273431f*ay + 0.56802827f*by - 0.54067466f*cy + Ay;
    g_Cb[i*3+2] = -0.58273431f*az + 0.56802827f*bz - 0.54067466f*cz + Az;
    g_C4[i] = make_float4(Cx, Cy, Cz, mask[i]);
}

// ============================================================
// Kernel 2: masked pairwise C-C distances + EXACT top-30 via
// histogram select + PARALLEL RANK placement.
// key = (adj_bits << 32) | j; bucket = key>>52 is monotone in adj.
// Candidates (all keys in buckets <= threshold bucket B) are a
// superset of the top-30. Keys are unique, so rank(key) =
// #candidates smaller than key gives the exact output slot;
// each thread ranks one candidate in parallel (no serial rounds).
// ============================================================
__global__ __launch_bounds__(256) void topk_kernel(float* __restrict__ outIdxF)
{
    int row = blockIdx.x;
    int b   = row / LSZ;
    int t   = threadIdx.x;
    int warp = t >> 5, lane = t & 31;

    __shared__ float wmax[8];
    __shared__ float sDmax;
    __shared__ uint32_t hist[NBUCK];
    __shared__ int sB;
    __shared__ int scnt;
    __shared__ unsigned long long cand[CAP];

    float4 me = g_C4[row];
    float mi = me.w;

    float dv[8], m2v[8];
    float lmax = 0.f;
    #pragma unroll
    for (int r = 0; r < 8; r++) {
        int j = t + r*256;
        float4 pj = g_C4[b*LSZ + j];
        float dx = me.x-pj.x, dy = me.y-pj.y, dz = me.z-pj.z;
        float d  = sqrtf(dx*dx + dy*dy + dz*dz + 1e-6f);
        float m2 = mi * pj.w;
        dv[r]  = m2 * d;
        m2v[r] = m2;
        lmax = fmaxf(lmax, dv[r]);
    }
    #pragma unroll
    for (int o = 16; o > 0; o >>= 1)
        lmax = fmaxf(lmax, __shfl_xor_sync(0xffffffffu, lmax, o));
    if (lane == 0) wmax[warp] = lmax;
    // zero histogram + counter while the max reduction settles
    #pragma unroll
    for (int h = 0; h < NBUCK/256; h++) hist[t + h*256] = 0;
    if (t == 0) scnt = 0;
    __syncthreads();
    if (t == 0) {
        float m = wmax[0];
        for (int w = 1; w < 8; w++) m = fmaxf(m, wmax[w]);
        sDmax = m;
    }
    __syncthreads();
    float Dmax = sDmax;

    unsigned long long key[8];
    #pragma unroll
    for (int r = 0; r < 8; r++) {
        float adj = dv[r] + (1.0f - m2v[r]) * Dmax;      // D_adjust
        key[r] = ((unsigned long long)__float_as_uint(adj) << 32)
               | (unsigned)(t + r*256);
        atomicAdd(&hist[(unsigned)(key[r] >> 52)], 1u);
    }
    __syncthreads();

    // warp 0: find threshold bucket B (cum count reaches KNB)
    if (warp == 0) {
        int base = lane * (NBUCK/32);
        int s = 0;
        #pragma unroll 8
        for (int c = 0; c < NBUCK/32; c++) s += (int)hist[base + c];
        int pre = s;
        #pragma unroll
        for (int o = 1; o < 32; o <<= 1) {
            int v = __shfl_up_sync(0xffffffffu, pre, o);
            if (lane >= o) pre += v;
        }
        pre -= s;                         // exclusive prefix
        if (pre < KNB && pre + s >= KNB) {
            int acc = pre, Bq = base + NBUCK/32 - 1;
            for (int c = 0; c < NBUCK/32; c++) {
                acc += (int)hist[base + c];
                if (acc >= KNB) { Bq = base + c; break; }
            }
            sB = Bq;
        }
    }
    __syncthreads();

    // compact candidates (all keys in buckets <= B; superset of top-30)
    int B = sB;
    #pragma unroll
    for (int r = 0; r < 8; r++) {
        if ((int)(unsigned)(key[r] >> 52) <= B) {
            int p = atomicAdd(&scnt, 1);
            if (p < CAP) cand[p] = key[r];
        }
    }
    __syncthreads();

    // parallel rank-select: rank = #cand smaller (keys unique).
    // Output slot is the rank; fully parallel, no serial rounds.
    int cnt = min(scnt, CAP);
    for (int i = t; i < cnt; i += 256) {
        unsigned long long k = cand[i];
        int rk = 0;
        for (int j = 0; j < cnt; j++)            // broadcast LDS.64 per j
            rk += (cand[j] < k) ? 1 : 0;
        if (rk < KNB) {
            int jm = (int)(unsigned)k;
            g_Eidx[row*KNB + rk] = jm;
            g_Dsel[row*KNB + rk] = __uint_as_float((unsigned)(k >> 32));
            if (outIdxF) outIdxF[row*KNB + rk] = (float)jm;
        }
    }
}

// ============================================================
// Kernel 3: edge features (16 RBF banks) -> bf16 hi/lo in global
// exp via FMA-pipe polynomial (no MUFU).
// ============================================================
__global__ __launch_bounds__(128) void feat_kernel(
    const float* __restrict__ X,
    const int*   __restrict__ ridx,
    const int*   __restrict__ chain)
{
    int row = blockIdx.x;
    int b   = row / LSZ;
    int t   = threadIdx.x;

    __shared__ float ia[4][3];
    __shared__ float ja[KNB][4][3];
    __shared__ int   jidx[KNB];
    __shared__ float dsel[KNB];
    __shared__ float dist[KNB][16];     // [0]=dsel, [1..15]=pair dists

    if (t < KNB) { jidx[t] = g_Eidx[row*KNB + t]; dsel[t] = g_Dsel[row*KNB + t]; }
    if (t >= 32 && t < 41) { int r = t - 32; ia[r/3][r%3] = X[row*12 + r]; }
    if (t >= 64 && t < 67) { ia[3][t-64] = g_Cb[row*3 + (t-64)]; }
    __syncthreads();

    for (int s = t; s < KNB*12; s += 128) {
        int k = s / 12, r = s % 12;
        int j = jidx[k];
        if (r < 9) ja[k][r/3][r%3] = X[(b*LSZ + j)*12 + r];
        else       ja[k][3][r-9]   = g_Cb[(b*LSZ + j)*3 + (r-9)];
    }
    if (t < KNB) {
        int j = jidx[t];
        int off  = ridx[row] - ridx[b*LSZ + j];
        int same = (chain[row] == chain[b*LSZ + j]);
        g_Dcode[row*KNB + t] = same ? min(max(off + MAXREL, 0), 2*MAXREL)
                                    : (2*MAXREL + 1);
        dist[t][0] = dsel[t];
    }
    __syncthreads();

    for (int s = t; s < KNB*16; s += 128) {
        int k = s >> 4, p = s & 15;
        if (p < 15) {
            int a = c_PA[p], bb = c_PB[p];
            float dx = ia[a][0] - ja[k][bb][0];
            float dy = ia[a][1] - ja[k][bb][1];
            float dz = ia[a][2] - ja[k][bb][2];
            dist[k][p+1] = sqrtf(dx*dx + dy*dy + dz*dz + 1e-6f);
        }
    }
    __syncthreads();

    // 256 channels per edge, emitted as 128 bf16x2 pairs (hi + lo)
    size_t base = (size_t)row * KNB * 128;
    for (int s = t; s < KNB*128; s += 128) {
        int k  = s >> 7;          // neighbor
        int pr = s & 127;         // pair index: channels 2pr, 2pr+1
        int c0 = pr*2, c1 = c0 + 1;
        float d0 = dist[k][c0 >> 4];
        float d1 = dist[k][c1 >> 4];
        float mu0 = 2.0f + (float)(c0 & 15) * (20.0f/15.0f);
        float mu1 = 2.0f + (float)(c1 & 15) * (20.0f/15.0f);
        float z0 = (d0 - mu0) * 0.8f;
        float z1 = (d1 - mu1) * 0.8f;
        float v0 = exp_neg(z0*z0);
        float v1 = exp_neg(z1*z1);
        __nv_bfloat16 h0 = __float2bfloat16(v0), h1 = __float2bfloat16(v1);
        float l0 = v0 - __bfloat162float(h0);
        float l1 = v1 - __bfloat162float(h1);
        g_Fh[base + s] = pack_bf16x2(h0, h1);
        g_Fl[base + s] = pack_bf16x2(__float2bfloat16(l0), __float2bfloat16(l1));
    }
}

// ============================================================
// Kernel 4: HMMA GEMM [128 edges x 256] @ [256 x 128] + Tpos +
// per-edge layernorm. 512 threads = 16 warps; warp (mh,nq) owns a
// 32x32 C tile. bf16 hi/lo split, 3 mma terms, fp32 accum.
// ============================================================
__global__ __launch_bounds__(512, 1) void gemm_kernel(
    const float* __restrict__ gamma,
    const float* __restrict__ beta,
    float*       __restrict__ outE)
{
    __shared__ __align__(16) __nv_bfloat16 Ah[128][ASTRIDE];
    __shared__ __align__(16) __nv_bfloat16 Al[128][ASTRIDE];
    __shared__ float rowsum[128], rowsq[128], smu[128], sinv[128];

    int t = threadIdx.x, lane = t & 31, w = t >> 5;
    int mh = w >> 2, nq = w & 3;         // warp tile: rows mh*32+, cols nq*32+
    int m0 = blockIdx.x * 128;
    int g  = lane >> 2, tg = lane & 3;

    if (t < 128) { rowsum[t] = 0.f; rowsq[t] = 0.f; }

    float C[2][4][4];
    #pragma unroll
    for (int mf = 0; mf < 2; mf++)
        #pragma unroll
        for (int nf = 0; nf < 4; nf++)
            #pragma unroll
            for (int i = 0; i < 4; i++) C[mf][nf][i] = 0.f;

    for (int kc = 0; kc < 4; kc++) {
        __syncthreads();
        // stage A chunk: 128 rows x 64 bf16 (hi + lo)
        #pragma unroll
        for (int u = 0; u < 4; u++) {
            int idx = t + 512*u;               // 0..2047
            int e = idx >> 4, un = idx & 15;
            size_t goff = (size_t)(m0 + e)*128 + kc*32 + un*2;
            uint2 vh = *reinterpret_cast<const uint2*>(&g_Fh[goff]);
            uint2 vl = *reinterpret_cast<const uint2*>(&g_Fl[goff]);
            *reinterpret_cast<uint2*>(&Ah[e][un*4]) = vh;
            *reinterpret_cast<uint2*>(&Al[e][un*4]) = vl;
        }
        __syncthreads();

        #pragma unroll
        for (int ks = 0; ks < 4; ks++) {
            uint2 bh[4], bl[4];
            int ksg = kc*4 + ks;
            #pragma unroll
            for (int nf = 0; nf < 4; nf++) {
                int gidx = (ksg*16 + nq*4 + nf)*32 + lane;
                bh[nf] = g_WfH[gidx];
                bl[nf] = g_WfL[gidx];
            }
            #pragma unroll
            for (int mf = 0; mf < 2; mf++) {
                int rr = mh*32 + mf*16 + (lane & 15);
                int cc = ks*16 + 8*(lane >> 4);
                uint32_t ah[4], al[4];
                ldsm_x4(ah, smem_to_u32(&Ah[rr][cc]));
                ldsm_x4(al, smem_to_u32(&Al[rr][cc]));
                #pragma unroll
                for (int nf = 0; nf < 4; nf++) {
                    mma_bf16(C[mf][nf], ah, reinterpret_cast<uint32_t*>(&bh[nf]));
                    mma_bf16(C[mf][nf], ah, reinterpret_cast<uint32_t*>(&bl[nf]));
                    mma_bf16(C[mf][nf], al, reinterpret_cast<uint32_t*>(&bh[nf]));
                }
            }
        }
    }

    // ---- epilogue: +Tpos, row sums (quad shfl + smem atomics) ----
    #pragma unroll
    for (int mf = 0; mf < 2; mf++) {
        int r0 = mh*32 + mf*16 + g;          // local rows r0, r0+8
        int dc0 = g_Dcode[m0 + r0];
        int dc1 = g_Dcode[m0 + r0 + 8];
        float s0 = 0.f, q0 = 0.f, s1 = 0.f, q1 = 0.f;
        #pragma unroll
        for (int nf = 0; nf < 4; nf++) {
            int col = nq*32 + nf*8 + tg*2;
            float2 t0 = *reinterpret_cast<const float2*>(&g_Tpos[dc0*NOUT + col]);
            float2 t1 = *reinterpret_cast<const float2*>(&g_Tpos[dc1*NOUT + col]);
            C[mf][nf][0] += t0.x;  C[mf][nf][1] += t0.y;
            C[mf][nf][2] += t1.x;  C[mf][nf][3] += t1.y;
            s0 += C[mf][nf][0] + C[mf][nf][1];
            q0 += C[mf][nf][0]*C[mf][nf][0] + C[mf][nf][1]*C[mf][nf][1];
            s1 += C[mf][nf][2] + C[mf][nf][3];
            q1 += C[mf][nf][2]*C[mf][nf][2] + C[mf][nf][3]*C[mf][nf][3];
        }
        s0 += __shfl_xor_sync(0xffffffffu, s0, 1);
        s0 += __shfl_xor_sync(0xffffffffu, s0, 2);
        q0 += __shfl_xor_sync(0xffffffffu, q0, 1);
        q0 += __shfl_xor_sync(0xffffffffu, q0, 2);
        s1 += __shfl_xor_sync(0xffffffffu, s1, 1);
        s1 += __shfl_xor_sync(0xffffffffu, s1, 2);
        q1 += __shfl_xor_sync(0xffffffffu, q1, 1);
        q1 += __shfl_xor_sync(0xffffffffu, q1, 2);
        if (tg == 0) {
            atomicAdd(&rowsum[r0],     s0);
            atomicAdd(&rowsq [r0],     q0);
            atomicAdd(&rowsum[r0 + 8], s1);
            atomicAdd(&rowsq [r0 + 8], q1);
        }
    }
    __syncthreads();
    if (t < 128) {
        float mu  = rowsum[t] * (1.0f/NOUT);
        float var = fmaxf(rowsq[t] * (1.0f/NOUT) - mu*mu, 0.0f);
        smu[t]  = mu;
        sinv[t] = rsqrtf(var + 1e-5f);
    }
    __syncthreads();

    #pragma unroll
    for (int mf = 0; mf < 2; mf++) {
        int r0 = mh*32 + mf*16 + g;
        float mu0 = smu[r0],   iv0 = sinv[r0];
        float mu1 = smu[r0+8], iv1 = sinv[r0+8];
        #pragma unroll
        for (int nf = 0; nf < 4; nf++) {
            int col = nq*32 + nf*8 + tg*2;
            float2 gm = *reinterpret_cast<const float2*>(&gamma[col]);
            float2 bt = *reinterpret_cast<const float2*>(&beta [col]);
            float2 o0, o1;
            o0.x = (C[mf][nf][0] - mu0)*iv0*gm.x + bt.x;
            o0.y = (C[mf][nf][1] - mu0)*iv0*gm.y + bt.y;
            o1.x = (C[mf][nf][2] - mu1)*iv1*gm.x + bt.x;
            o1.y = (C[mf][nf][3] - mu1)*iv1*gm.y + bt.y;
            *reinterpret_cast<float2*>(&outE[(size_t)(m0 + r0    )*NOUT + col]) = o0;
            *reinterpret_cast<float2*>(&outE[(size_t)(m0 + r0 + 8)*NOUT + col]) = o1;
        }
    }
}

// ============================================================
extern "C" void kernel_launch(void* const* d_in, const int* in_sizes, int n_in,
                              void* d_out, int out_size)
{
    const float* X      = (const float*)d_in[0];
    const float* mask   = (const float*)d_in[1];
    const int*   ridx   = (const int*)  d_in[2];
    const int*   chain  = (const int*)  d_in[3];
    const float* W_pos  = (const float*)d_in[4];
    const float* b_pos  = (const float*)d_in[5];
    const float* W_edge = (const float*)d_in[6];
    const float* gamma  = (const float*)d_in[7];
    const float* beta   = (const float*)d_in[8];

    float* outE = (float*)d_out;
    long long esz = (long long)NEDGE*NOUT;           // 31,457,280
    float* outIdxF = ((long long)out_size > esz) ? (outE + esz) : nullptr;

    tpos_kernel<<<NDC, NOUT>>>(W_pos, b_pos, W_edge);
    wprep_kernel<<<32, 256>>>(W_edge);
    cb_kernel  <<<(BSZ*LSZ + 255)/256, 256>>>(X, mask);
    topk_kernel<<<BSZ*LSZ, 256>>>(outIdxF);
    feat_kernel<<<BSZ*LSZ, 128>>>(X, ridx, chain);
    gemm_kernel<<<MTILES, 512>>>(gamma, beta, outE);
}